// round 7
// baseline (speedup 1.0000x reference)
#include <cuda_runtime.h>
#include <cstdint>
#include <math.h>

#define N_    64
#define C_    128
#define K_    64
#define P_    4096
#define ALPHA_ 50.0f
#define EPS_  1e-12f

typedef unsigned long long ull;

// ---------------- scratch ----------------
__device__ float g_partial[N_ * 4 * K_ * C_];   // [n][ps][k][c]  (8MB)
__device__ float g_sasum[N_ * 4 * K_];          // [n][ps][k]

// ---------------- f32x2 helpers ----------------
__device__ __forceinline__ ull pk2(float a, float b) {
    ull r;
    asm("mov.b64 %0, {%1, %2};" : "=l"(r) : "r"(__float_as_uint(a)), "r"(__float_as_uint(b)));
    return r;
}
__device__ __forceinline__ void upk2(ull v, float& a, float& b) {
    unsigned int x, y;
    asm("mov.b64 {%0, %1}, %2;" : "=r"(x), "=r"(y) : "l"(v));
    a = __uint_as_float(x); b = __uint_as_float(y);
}
#define FMA2_(d, a, b) asm("fma.rn.f32x2 %0, %1, %2, %3;" : "=l"(d) : "l"(a), "l"(b), "l"(d))

// ---------------- fused mega kernel ----------------
// grid (4, 64): block = (n, 1024-pixel slice), 16 subtiles of 64 pixels.
// Strides = 70 floats (280B): 8B-aligned only -> ALL smem accesses on these
// tiles are <=8B. Conflict-free GEMM2 (row step 280 = 24 mod 128 -> 16 rows
// tile all banks; 8-row step 2240 = 64 mod 128 -> xf pair split).
#define XF_STR 70
#define SA_STR 70

__global__ __launch_bounds__(256, 2) void kMega(const float* __restrict__ x,
                                                const float* __restrict__ W,
                                                const float* __restrict__ bias,
                                                float* __restrict__ logits_out) {
    extern __shared__ float sm[];
    float* ws   = sm;                        // [c][k]      8192 fl
    float* xf   = sm + C_ * K_;              // [c][XF_STR] 8960 fl
    float* sas  = xf + C_ * XF_STR;          // [k][SA_STR] 4480 fl (also scratch)
    float* bs   = sas + K_ * SA_STR;         // [64]
    float* invv = bs + 64;                   // [64] 1/max(||x||,eps) per pixel
    float* nrm  = invv + 64;                 // [64] ||x|| per pixel

    const int tid = threadIdx.x;
    const int n   = blockIdx.y;
    const int ps  = blockIdx.x;              // 0..3

    // ---- prologue: load W, column-normalize into ws (xf as scratch) ----
    for (int i = tid; i < C_ * K_; i += 256) ws[i] = W[i];
    if (tid < 64) bs[tid] = bias[tid];
    __syncthreads();
    {
        const int k = tid & 63, q = tid >> 6;
        float ss = 0.f;
        #pragma unroll 8
        for (int c = q * 32; c < q * 32 + 32; ++c) {
            float v = ws[c * K_ + k];
            ss = fmaf(v, v, ss);
        }
        xf[q * 64 + k] = ss;
    }
    __syncthreads();
    if (tid < 64) {
        float tot = xf[tid] + xf[64 + tid] + xf[128 + tid] + xf[192 + tid];
        xf[256 + tid] = 1.f / fmaxf(sqrtf(tot), EPS_);
    }
    __syncthreads();
    for (int i = tid; i < C_ * K_; i += 256) ws[i] *= xf[256 + (i & 63)];
    __syncthreads();

    // role mappings
    const int pq  = tid & 15, cq = tid >> 4;   // loader
    const int pg  = tid & 15, kg = tid >> 4;   // GEMM1
    const int kg2 = tid & 15, cg = tid >> 4;   // GEMM2: k = kg2 + 16*kq, c = cg*8+m
    const int pN  = tid >> 2, qN = tid & 3;    // softmax
    const int kS  = tid & 63, part = tid >> 6; // sasum

    ull acc2[4][8];
    #pragma unroll
    for (int a = 0; a < 4; ++a)
        #pragma unroll
        for (int b = 0; b < 8; ++b) acc2[a][b] = 0ull;
    float sasum_reg = 0.f;

    const float* xbase = x + (size_t)n * C_ * P_ + ps * 1024;
    float* lb = logits_out + (size_t)n * K_ * P_ + ps * 1024;

    for (int sub = 0; sub < 16; ++sub) {
        const int p0 = sub * 64;

        // ---- load raw x tile [c][p] (8B smem stores) + sumsq partials ----
        {
            const float* xp = xbase + p0 + pq * 4;
            float s0 = 0.f, s1 = 0.f, s2 = 0.f, s3 = 0.f;
            #pragma unroll
            for (int i = 0; i < 8; ++i) {
                int c = cq + 16 * i;
                float4 v = *(const float4*)(xp + (size_t)c * P_);
                *(float2*)(xf + c * XF_STR + pq * 4)     = make_float2(v.x, v.y);
                *(float2*)(xf + c * XF_STR + pq * 4 + 2) = make_float2(v.z, v.w);
                s0 = fmaf(v.x, v.x, s0);
                s1 = fmaf(v.y, v.y, s1);
                s2 = fmaf(v.z, v.z, s2);
                s3 = fmaf(v.w, v.w, s3);
            }
            sas[cq * 64 + pq * 4 + 0] = s0;
            sas[cq * 64 + pq * 4 + 1] = s1;
            sas[cq * 64 + pq * 4 + 2] = s2;
            sas[cq * 64 + pq * 4 + 3] = s3;
        }
        __syncthreads();

        // ---- invn compute (t<64) overlaps start of GEMM1 ----
        if (tid < 64) {
            float tot = 0.f;
            #pragma unroll
            for (int q = 0; q < 16; ++q) tot += sas[q * 64 + tid];
            float nr = sqrtf(tot);
            nrm[tid]  = nr;
            invv[tid] = 1.f / fmaxf(nr, EPS_);
        }

        // ---- GEMM1: dot[4k x 4p] over 128 c (raw x, 8B xf loads) ----
        ull a0[4], a1[4];
        #pragma unroll
        for (int kq = 0; kq < 4; ++kq) { a0[kq] = 0ull; a1[kq] = 0ull; }
        #pragma unroll 4
        for (int c = 0; c < C_; ++c) {
            ull xlo = *(const ull*)(xf + c * XF_STR + pg * 4);
            ull xhi = *(const ull*)(xf + c * XF_STR + pg * 4 + 2);
            float4 w4 = *(const float4*)(ws + c * K_ + kg * 4);
            ull w;
            w = pk2(w4.x, w4.x); FMA2_(a0[0], w, xlo); FMA2_(a1[0], w, xhi);
            w = pk2(w4.y, w4.y); FMA2_(a0[1], w, xlo); FMA2_(a1[1], w, xhi);
            w = pk2(w4.z, w4.z); FMA2_(a0[2], w, xlo); FMA2_(a1[2], w, xhi);
            w = pk2(w4.w, w4.w); FMA2_(a0[3], w, xlo); FMA2_(a1[3], w, xhi);
        }
        __syncthreads();   // invn ready; sas scratch free for logits

        // ---- scale by invn, write logits (gmem float4 + sas 2x float2) ----
        {
            float i0 = invv[pg * 4 + 0];
            float i1 = invv[pg * 4 + 1];
            float i2 = invv[pg * 4 + 2];
            float i3 = invv[pg * 4 + 3];
            #pragma unroll
            for (int kq = 0; kq < 4; ++kq) {
                float l0, l1, l2, l3;
                upk2(a0[kq], l0, l1);
                upk2(a1[kq], l2, l3);
                l0 *= i0; l1 *= i1; l2 *= i2; l3 *= i3;
                int k = kg * 4 + kq;
                *(float4*)(lb + (size_t)k * P_ + p0 + pg * 4) = make_float4(l0, l1, l2, l3);
                *(float2*)(sas + k * SA_STR + pg * 4)     = make_float2(l0, l1);
                *(float2*)(sas + k * SA_STR + pg * 4 + 2) = make_float2(l2, l3);
            }
        }
        __syncthreads();

        // ---- softmax over k per pixel; write sa * invn[p] into sas ----
        {
            float lv[16];
            float m = -3.4e38f;
            #pragma unroll
            for (int i = 0; i < 16; ++i) {
                int k = qN + 4 * i;
                float t = (sas[k * SA_STR + pN] + bs[k]) * ALPHA_;
                lv[i] = t; m = fmaxf(m, t);
            }
            m = fmaxf(m, __shfl_xor_sync(0xffffffffu, m, 1));
            m = fmaxf(m, __shfl_xor_sync(0xffffffffu, m, 2));
            float s = 0.f;
            #pragma unroll
            for (int i = 0; i < 16; ++i) {
                float e = __expf(lv[i] - m);
                lv[i] = e; s += e;
            }
            s += __shfl_xor_sync(0xffffffffu, s, 1);
            s += __shfl_xor_sync(0xffffffffu, s, 2);
            float rsi = (1.f / s) * invv[pN];    // fold invn into sa
            #pragma unroll
            for (int i = 0; i < 16; ++i)
                sas[(qN + 4 * i) * SA_STR + pN] = lv[i] * rsi;
        }
        __syncthreads();

        // ---- sasum partial: sa = sas * nrm (undo invn fold) ----
        {
            float s = 0.f;
            #pragma unroll
            for (int i = 0; i < 16; ++i)
                s = fmaf(sas[kS * SA_STR + part * 16 + i], nrm[part * 16 + i], s);
            sasum_reg += s;
        }

        // ---- GEMM2: acc2[4k x 8c] over 32 p-pairs (all 8B loads) ----
        {
            #pragma unroll 2
            for (int j = 0; j < 32; ++j) {
                ull s0 = *(const ull*)(sas + (kg2 +  0) * SA_STR + 2 * j);
                ull s1 = *(const ull*)(sas + (kg2 + 16) * SA_STR + 2 * j);
                ull s2 = *(const ull*)(sas + (kg2 + 32) * SA_STR + 2 * j);
                ull s3 = *(const ull*)(sas + (kg2 + 48) * SA_STR + 2 * j);
                ull xv0 = *(const ull*)(xf + (cg * 8 + 0) * XF_STR + 2 * j);
                ull xv1 = *(const ull*)(xf + (cg * 8 + 1) * XF_STR + 2 * j);
                ull xv2 = *(const ull*)(xf + (cg * 8 + 2) * XF_STR + 2 * j);
                ull xv3 = *(const ull*)(xf + (cg * 8 + 3) * XF_STR + 2 * j);
                ull xv4 = *(const ull*)(xf + (cg * 8 + 4) * XF_STR + 2 * j);
                ull xv5 = *(const ull*)(xf + (cg * 8 + 5) * XF_STR + 2 * j);
                ull xv6 = *(const ull*)(xf + (cg * 8 + 6) * XF_STR + 2 * j);
                ull xv7 = *(const ull*)(xf + (cg * 8 + 7) * XF_STR + 2 * j);
                FMA2_(acc2[0][0], s0, xv0); FMA2_(acc2[0][1], s0, xv1);
                FMA2_(acc2[0][2], s0, xv2); FMA2_(acc2[0][3], s0, xv3);
                FMA2_(acc2[0][4], s0, xv4); FMA2_(acc2[0][5], s0, xv5);
                FMA2_(acc2[0][6], s0, xv6); FMA2_(acc2[0][7], s0, xv7);
                FMA2_(acc2[1][0], s1, xv0); FMA2_(acc2[1][1], s1, xv1);
                FMA2_(acc2[1][2], s1, xv2); FMA2_(acc2[1][3], s1, xv3);
                FMA2_(acc2[1][4], s1, xv4); FMA2_(acc2[1][5], s1, xv5);
                FMA2_(acc2[1][6], s1, xv6); FMA2_(acc2[1][7], s1, xv7);
                FMA2_(acc2[2][0], s2, xv0); FMA2_(acc2[2][1], s2, xv1);
                FMA2_(acc2[2][2], s2, xv2); FMA2_(acc2[2][3], s2, xv3);
                FMA2_(acc2[2][4], s2, xv4); FMA2_(acc2[2][5], s2, xv5);
                FMA2_(acc2[2][6], s2, xv6); FMA2_(acc2[2][7], s2, xv7);
                FMA2_(acc2[3][0], s3, xv0); FMA2_(acc2[3][1], s3, xv1);
                FMA2_(acc2[3][2], s3, xv2); FMA2_(acc2[3][3], s3, xv3);
                FMA2_(acc2[3][4], s3, xv4); FMA2_(acc2[3][5], s3, xv5);
                FMA2_(acc2[3][6], s3, xv6); FMA2_(acc2[3][7], s3, xv7);
            }
        }
        __syncthreads();
    }

    // ---- write GEMM2 split partials (fold p-parity halves) ----
    {
        float* pp = g_partial + ((size_t)(n * 4 + ps) * K_) * C_;
        #pragma unroll
        for (int kq = 0; kq < 4; ++kq) {
            int k = kg2 + 16 * kq;
            #pragma unroll
            for (int m = 0; m < 8; ++m) {
                float u0, u1;
                upk2(acc2[kq][m], u0, u1);
                pp[k * C_ + cg * 8 + m] = u0 + u1;
            }
        }
    }

    // ---- reduce sasum parts ----
    sas[part * 64 + kS] = sasum_reg;
    __syncthreads();
    if (tid < 64)
        g_sasum[(n * 4 + ps) * 64 + tid] =
            sas[tid] + sas[64 + tid] + sas[128 + tid] + sas[192 + tid];
}

// ---------------- kernel D: combine + subtract + intra-norm + global/8 ----------------
__global__ __launch_bounds__(128) void kD(const float* __restrict__ W,
                                          float* __restrict__ vlad_out) {
    __shared__ float red[128];
    const int b = blockIdx.x;
    const int n = b >> 6, k = b & 63, tid = threadIdx.x;

    float sasum = 0.f;
    #pragma unroll
    for (int ps = 0; ps < 4; ++ps) sasum += g_sasum[(n * 4 + ps) * 64 + k];

    float v = 0.f;
    #pragma unroll
    for (int ps = 0; ps < 4; ++ps)
        v += g_partial[((size_t)(n * 4 + ps) * K_ + k) * C_ + tid];
    v = fmaf(-sasum, W[tid * K_ + k], v);

    red[tid] = v * v; __syncthreads();
    #pragma unroll
    for (int o = 64; o > 0; o >>= 1) { if (tid < o) red[tid] += red[tid + o]; __syncthreads(); }
    // intra-norm; global L2 over 64 unit-norm rows is exactly sqrt(64)=8
    float inv = 0.125f / fmaxf(sqrtf(red[0]), EPS_);
    vlad_out[((size_t)n * K_ + k) * C_ + tid] = v * inv;
}

// ---------------- launch ----------------
extern "C" void kernel_launch(void* const* d_in, const int* in_sizes, int n_in,
                              void* d_out, int out_size) {
    const float* x    = (const float*)d_in[0];
    const float* W    = (const float*)d_in[1];
    const float* bias = (const float*)d_in[2];
    float* out        = (float*)d_out;
    float* vlad_out   = out;                               // [64, 8192]
    float* logits_out = out + (size_t)N_ * K_ * C_;        // [64, 64, 4096]

    const int smemM = (C_ * K_ + C_ * XF_STR + K_ * SA_STR + 192) * (int)sizeof(float);
    static bool attr_set = false;
    if (!attr_set) {
        cudaFuncSetAttribute(kMega, cudaFuncAttributeMaxDynamicSharedMemorySize, smemM);
        attr_set = true;
    }

    dim3 gM(4, N_);
    kMega<<<gM, 256, smemM>>>(x, W, bias, logits_out);

    kD<<<N_ * K_, 128>>>(W, vlad_out);
}

// round 8
// speedup vs baseline: 1.0009x; 1.0009x over previous
#include <cuda_runtime.h>
#include <cstdint>
#include <math.h>

#define N_    64
#define C_    128
#define K_    64
#define P_    4096
#define ALPHA_ 50.0f
#define EPS_  1e-12f

typedef unsigned long long ull;

// ---------------- scratch ----------------
__device__ float g_partial[N_ * 4 * K_ * C_];   // [n][ps][k][c]  (8MB)
__device__ float g_sasum[N_ * 4 * K_];          // [n][ps][k]

// ---------------- f32x2 helpers ----------------
__device__ __forceinline__ ull pk2(float a, float b) {
    ull r;
    asm("mov.b64 %0, {%1, %2};" : "=l"(r) : "r"(__float_as_uint(a)), "r"(__float_as_uint(b)));
    return r;
}
__device__ __forceinline__ void upk2(ull v, float& a, float& b) {
    unsigned int x, y;
    asm("mov.b64 {%0, %1}, %2;" : "=r"(x), "=r"(y) : "l"(v));
    a = __uint_as_float(x); b = __uint_as_float(y);
}
#define FMA2_(d, a, b) asm("fma.rn.f32x2 %0, %1, %2, %3;" : "=l"(d) : "l"(a), "l"(b), "l"(d))

// ---------------- fused mega kernel ----------------
// grid (4, 64): block = (n, 1024-pixel slice), 16 subtiles of 64 pixels.
// Strides = 70 floats (280B): 8B-aligned only -> ALL smem accesses on these
// tiles are <=8B. Conflict-free GEMM2 (row step 280 = 24 mod 128 -> 16 rows
// tile all banks; 8-row step 2240 = 64 mod 128 -> xf pair split).
#define XF_STR 70
#define SA_STR 70

__global__ __launch_bounds__(256, 2) void kMega(const float* __restrict__ x,
                                                const float* __restrict__ W,
                                                const float* __restrict__ bias,
                                                float* __restrict__ logits_out) {
    extern __shared__ float sm[];
    float* ws   = sm;                        // [c][k]      8192 fl
    float* xf   = sm + C_ * K_;              // [c][XF_STR] 8960 fl
    float* sas  = xf + C_ * XF_STR;          // [k][SA_STR] 4480 fl (also scratch)
    float* bs   = sas + K_ * SA_STR;         // [64]
    float* invv = bs + 64;                   // [64] 1/max(||x||,eps) per pixel
    float* nrm  = invv + 64;                 // [64] ||x|| per pixel

    const int tid = threadIdx.x;
    const int n   = blockIdx.y;
    const int ps  = blockIdx.x;              // 0..3

    // ---- prologue: load W, column-normalize into ws (xf as scratch) ----
    for (int i = tid; i < C_ * K_; i += 256) ws[i] = W[i];
    if (tid < 64) bs[tid] = bias[tid];
    __syncthreads();
    {
        const int k = tid & 63, q = tid >> 6;
        float ss = 0.f;
        #pragma unroll 8
        for (int c = q * 32; c < q * 32 + 32; ++c) {
            float v = ws[c * K_ + k];
            ss = fmaf(v, v, ss);
        }
        xf[q * 64 + k] = ss;
    }
    __syncthreads();
    if (tid < 64) {
        float tot = xf[tid] + xf[64 + tid] + xf[128 + tid] + xf[192 + tid];
        xf[256 + tid] = 1.f / fmaxf(sqrtf(tot), EPS_);
    }
    __syncthreads();
    for (int i = tid; i < C_ * K_; i += 256) ws[i] *= xf[256 + (i & 63)];
    __syncthreads();

    // role mappings
    const int pq  = tid & 15, cq = tid >> 4;   // loader
    const int pg  = tid & 15, kg = tid >> 4;   // GEMM1
    const int kg2 = tid & 15, cg = tid >> 4;   // GEMM2: k = kg2 + 16*kq, c = cg*8+m
    const int pN  = tid >> 2, qN = tid & 3;    // softmax
    const int kS  = tid & 63, part = tid >> 6; // sasum

    ull acc2[4][8];
    #pragma unroll
    for (int a = 0; a < 4; ++a)
        #pragma unroll
        for (int b = 0; b < 8; ++b) acc2[a][b] = 0ull;
    float sasum_reg = 0.f;

    const float* xbase = x + (size_t)n * C_ * P_ + ps * 1024;
    float* lb = logits_out + (size_t)n * K_ * P_ + ps * 1024;

    for (int sub = 0; sub < 16; ++sub) {
        const int p0 = sub * 64;

        // ---- load raw x tile [c][p] (8B smem stores) + sumsq partials ----
        {
            const float* xp = xbase + p0 + pq * 4;
            float s0 = 0.f, s1 = 0.f, s2 = 0.f, s3 = 0.f;
            #pragma unroll
            for (int i = 0; i < 8; ++i) {
                int c = cq + 16 * i;
                float4 v = *(const float4*)(xp + (size_t)c * P_);
                *(float2*)(xf + c * XF_STR + pq * 4)     = make_float2(v.x, v.y);
                *(float2*)(xf + c * XF_STR + pq * 4 + 2) = make_float2(v.z, v.w);
                s0 = fmaf(v.x, v.x, s0);
                s1 = fmaf(v.y, v.y, s1);
                s2 = fmaf(v.z, v.z, s2);
                s3 = fmaf(v.w, v.w, s3);
            }
            sas[cq * 64 + pq * 4 + 0] = s0;
            sas[cq * 64 + pq * 4 + 1] = s1;
            sas[cq * 64 + pq * 4 + 2] = s2;
            sas[cq * 64 + pq * 4 + 3] = s3;
        }
        __syncthreads();

        // ---- invn compute (t<64) overlaps start of GEMM1 ----
        if (tid < 64) {
            float tot = 0.f;
            #pragma unroll
            for (int q = 0; q < 16; ++q) tot += sas[q * 64 + tid];
            float nr = sqrtf(tot);
            nrm[tid]  = nr;
            invv[tid] = 1.f / fmaxf(nr, EPS_);
        }

        // ---- GEMM1: dot[4k x 4p] over 128 c (raw x, 8B xf loads) ----
        ull a0[4], a1[4];
        #pragma unroll
        for (int kq = 0; kq < 4; ++kq) { a0[kq] = 0ull; a1[kq] = 0ull; }
        #pragma unroll 4
        for (int c = 0; c < C_; ++c) {
            ull xlo = *(const ull*)(xf + c * XF_STR + pg * 4);
            ull xhi = *(const ull*)(xf + c * XF_STR + pg * 4 + 2);
            float4 w4 = *(const float4*)(ws + c * K_ + kg * 4);
            ull w;
            w = pk2(w4.x, w4.x); FMA2_(a0[0], w, xlo); FMA2_(a1[0], w, xhi);
            w = pk2(w4.y, w4.y); FMA2_(a0[1], w, xlo); FMA2_(a1[1], w, xhi);
            w = pk2(w4.z, w4.z); FMA2_(a0[2], w, xlo); FMA2_(a1[2], w, xhi);
            w = pk2(w4.w, w4.w); FMA2_(a0[3], w, xlo); FMA2_(a1[3], w, xhi);
        }
        __syncthreads();   // invn ready; sas scratch free for logits

        // ---- scale by invn, write logits (gmem float4 + sas 2x float2) ----
        {
            float i0 = invv[pg * 4 + 0];
            float i1 = invv[pg * 4 + 1];
            float i2 = invv[pg * 4 + 2];
            float i3 = invv[pg * 4 + 3];
            #pragma unroll
            for (int kq = 0; kq < 4; ++kq) {
                float l0, l1, l2, l3;
                upk2(a0[kq], l0, l1);
                upk2(a1[kq], l2, l3);
                l0 *= i0; l1 *= i1; l2 *= i2; l3 *= i3;
                int k = kg * 4 + kq;
                *(float4*)(lb + (size_t)k * P_ + p0 + pg * 4) = make_float4(l0, l1, l2, l3);
                *(float2*)(sas + k * SA_STR + pg * 4)     = make_float2(l0, l1);
                *(float2*)(sas + k * SA_STR + pg * 4 + 2) = make_float2(l2, l3);
            }
        }
        __syncthreads();

        // ---- softmax over k per pixel; write sa * invn[p] into sas ----
        {
            float lv[16];
            float m = -3.4e38f;
            #pragma unroll
            for (int i = 0; i < 16; ++i) {
                int k = qN + 4 * i;
                float t = (sas[k * SA_STR + pN] + bs[k]) * ALPHA_;
                lv[i] = t; m = fmaxf(m, t);
            }
            m = fmaxf(m, __shfl_xor_sync(0xffffffffu, m, 1));
            m = fmaxf(m, __shfl_xor_sync(0xffffffffu, m, 2));
            float s = 0.f;
            #pragma unroll
            for (int i = 0; i < 16; ++i) {
                float e = __expf(lv[i] - m);
                lv[i] = e; s += e;
            }
            s += __shfl_xor_sync(0xffffffffu, s, 1);
            s += __shfl_xor_sync(0xffffffffu, s, 2);
            float rsi = (1.f / s) * invv[pN];    // fold invn into sa
            #pragma unroll
            for (int i = 0; i < 16; ++i)
                sas[(qN + 4 * i) * SA_STR + pN] = lv[i] * rsi;
        }
        __syncthreads();

        // ---- sasum partial: sa = sas * nrm (undo invn fold) ----
        {
            float s = 0.f;
            #pragma unroll
            for (int i = 0; i < 16; ++i)
                s = fmaf(sas[kS * SA_STR + part * 16 + i], nrm[part * 16 + i], s);
            sasum_reg += s;
        }

        // ---- GEMM2: acc2[4k x 8c] over 32 p-pairs (all 8B loads) ----
        {
            #pragma unroll 2
            for (int j = 0; j < 32; ++j) {
                ull s0 = *(const ull*)(sas + (kg2 +  0) * SA_STR + 2 * j);
                ull s1 = *(const ull*)(sas + (kg2 + 16) * SA_STR + 2 * j);
                ull s2 = *(const ull*)(sas + (kg2 + 32) * SA_STR + 2 * j);
                ull s3 = *(const ull*)(sas + (kg2 + 48) * SA_STR + 2 * j);
                ull xv0 = *(const ull*)(xf + (cg * 8 + 0) * XF_STR + 2 * j);
                ull xv1 = *(const ull*)(xf + (cg * 8 + 1) * XF_STR + 2 * j);
                ull xv2 = *(const ull*)(xf + (cg * 8 + 2) * XF_STR + 2 * j);
                ull xv3 = *(const ull*)(xf + (cg * 8 + 3) * XF_STR + 2 * j);
                ull xv4 = *(const ull*)(xf + (cg * 8 + 4) * XF_STR + 2 * j);
                ull xv5 = *(const ull*)(xf + (cg * 8 + 5) * XF_STR + 2 * j);
                ull xv6 = *(const ull*)(xf + (cg * 8 + 6) * XF_STR + 2 * j);
                ull xv7 = *(const ull*)(xf + (cg * 8 + 7) * XF_STR + 2 * j);
                FMA2_(acc2[0][0], s0, xv0); FMA2_(acc2[0][1], s0, xv1);
                FMA2_(acc2[0][2], s0, xv2); FMA2_(acc2[0][3], s0, xv3);
                FMA2_(acc2[0][4], s0, xv4); FMA2_(acc2[0][5], s0, xv5);
                FMA2_(acc2[0][6], s0, xv6); FMA2_(acc2[0][7], s0, xv7);
                FMA2_(acc2[1][0], s1, xv0); FMA2_(acc2[1][1], s1, xv1);
                FMA2_(acc2[1][2], s1, xv2); FMA2_(acc2[1][3], s1, xv3);
                FMA2_(acc2[1][4], s1, xv4); FMA2_(acc2[1][5], s1, xv5);
                FMA2_(acc2[1][6], s1, xv6); FMA2_(acc2[1][7], s1, xv7);
                FMA2_(acc2[2][0], s2, xv0); FMA2_(acc2[2][1], s2, xv1);
                FMA2_(acc2[2][2], s2, xv2); FMA2_(acc2[2][3], s2, xv3);
                FMA2_(acc2[2][4], s2, xv4); FMA2_(acc2[2][5], s2, xv5);
                FMA2_(acc2[2][6], s2, xv6); FMA2_(acc2[2][7], s2, xv7);
                FMA2_(acc2[3][0], s3, xv0); FMA2_(acc2[3][1], s3, xv1);
                FMA2_(acc2[3][2], s3, xv2); FMA2_(acc2[3][3], s3, xv3);
                FMA2_(acc2[3][4], s3, xv4); FMA2_(acc2[3][5], s3, xv5);
                FMA2_(acc2[3][6], s3, xv6); FMA2_(acc2[3][7], s3, xv7);
            }
        }
        __syncthreads();
    }

    // ---- write GEMM2 split partials (fold p-parity halves) ----
    {
        float* pp = g_partial + ((size_t)(n * 4 + ps) * K_) * C_;
        #pragma unroll
        for (int kq = 0; kq < 4; ++kq) {
            int k = kg2 + 16 * kq;
            #pragma unroll
            for (int m = 0; m < 8; ++m) {
                float u0, u1;
                upk2(acc2[kq][m], u0, u1);
                pp[k * C_ + cg * 8 + m] = u0 + u1;
            }
        }
    }

    // ---- reduce sasum parts ----
    sas[part * 64 + kS] = sasum_reg;
    __syncthreads();
    if (tid < 64)
        g_sasum[(n * 4 + ps) * 64 + tid] =
            sas[tid] + sas[64 + tid] + sas[128 + tid] + sas[192 + tid];
}

// ---------------- kernel D: combine + subtract + intra-norm + global/8 ----------------
__global__ __launch_bounds__(128) void kD(const float* __restrict__ W,
                                          float* __restrict__ vlad_out) {
    __shared__ float red[128];
    const int b = blockIdx.x;
    const int n = b >> 6, k = b & 63, tid = threadIdx.x;

    float sasum = 0.f;
    #pragma unroll
    for (int ps = 0; ps < 4; ++ps) sasum += g_sasum[(n * 4 + ps) * 64 + k];

    float v = 0.f;
    #pragma unroll
    for (int ps = 0; ps < 4; ++ps)
        v += g_partial[((size_t)(n * 4 + ps) * K_ + k) * C_ + tid];
    v = fmaf(-sasum, W[tid * K_ + k], v);

    red[tid] = v * v; __syncthreads();
    #pragma unroll
    for (int o = 64; o > 0; o >>= 1) { if (tid < o) red[tid] += red[tid + o]; __syncthreads(); }
    // intra-norm; global L2 over 64 unit-norm rows is exactly sqrt(64)=8
    float inv = 0.125f / fmaxf(sqrtf(red[0]), EPS_);
    vlad_out[((size_t)n * K_ + k) * C_ + tid] = v * inv;
}

// ---------------- launch ----------------
extern "C" void kernel_launch(void* const* d_in, const int* in_sizes, int n_in,
                              void* d_out, int out_size) {
    const float* x    = (const float*)d_in[0];
    const float* W    = (const float*)d_in[1];
    const float* bias = (const float*)d_in[2];
    float* out        = (float*)d_out;
    float* vlad_out   = out;                               // [64, 8192]
    float* logits_out = out + (size_t)N_ * K_ * C_;        // [64, 64, 4096]

    const int smemM = (C_ * K_ + C_ * XF_STR + K_ * SA_STR + 192) * (int)sizeof(float);
    static bool attr_set = false;
    if (!attr_set) {
        cudaFuncSetAttribute(kMega, cudaFuncAttributeMaxDynamicSharedMemorySize, smemM);
        attr_set = true;
    }

    dim3 gM(4, N_);
    kMega<<<gM, 256, smemM>>>(x, W, bias, logits_out);

    kD<<<N_ * K_, 128>>>(W, vlad_out);
}

// round 9
// speedup vs baseline: 1.0339x; 1.0330x over previous
#include <cuda_runtime.h>
#include <cstdint>
#include <math.h>

#define N_    64
#define C_    128
#define K_    64
#define P_    4096
#define ALPHA_ 50.0f
#define EPS_  1e-12f

typedef unsigned long long ull;

// ---------------- scratch ----------------
__device__ float g_partial[N_ * 4 * K_ * C_];   // [n][ps][k][c]  (8MB)
__device__ float g_sasum[N_ * 4 * K_];          // [n][ps][k]

// ---------------- f32x2 helpers ----------------
__device__ __forceinline__ ull pk2(float a, float b) {
    ull r;
    asm("mov.b64 %0, {%1, %2};" : "=l"(r) : "r"(__float_as_uint(a)), "r"(__float_as_uint(b)));
    return r;
}
__device__ __forceinline__ void upk2(ull v, float& a, float& b) {
    unsigned int x, y;
    asm("mov.b64 {%0, %1}, %2;" : "=r"(x), "=r"(y) : "l"(v));
    a = __uint_as_float(x); b = __uint_as_float(y);
}
#define FMA2_(d, a, b) asm("fma.rn.f32x2 %0, %1, %2, %3;" : "=l"(d) : "l"(a), "l"(b), "l"(d))

// ---------------- fused mega kernel ----------------
// grid (4, 64): block = (n, 1024-pixel slice), 16 subtiles of 64 pixels.
// Strides 68 floats (272B, 16B-aligned). sas rows with bit3(k)=1 are
// column-rotated by +2 (mod 64) -> GEMM2 s-loads conflict-free.
#define XF_STR 68
#define SA_STR 68

__global__ __launch_bounds__(256, 2) void kMega(const float* __restrict__ x,
                                                const float* __restrict__ W,
                                                const float* __restrict__ bias,
                                                float* __restrict__ logits_out) {
    extern __shared__ float sm[];
    float* ws   = sm;                        // [c][k]      8192 fl
    float* xf   = sm + C_ * K_;              // [c][XF_STR] 8704 fl (raw x)
    float* sas  = xf + C_ * XF_STR;          // [k][SA_STR] 4352 fl (also scratch)
    float* bs   = sas + K_ * SA_STR;         // [64]
    float* invv = bs + 64;                   // [64] 1/max(||x||,eps)
    float* nrm  = invv + 64;                 // [64] ||x||

    const int tid = threadIdx.x;
    const int n   = blockIdx.y;
    const int ps  = blockIdx.x;              // 0..3

    // ---- prologue: load W, column-normalize into ws (xf as scratch) ----
    for (int i = tid; i < C_ * K_; i += 256) ws[i] = W[i];
    if (tid < 64) bs[tid] = bias[tid];
    __syncthreads();
    {
        const int k = tid & 63, q = tid >> 6;
        float ss = 0.f;
        #pragma unroll 8
        for (int c = q * 32; c < q * 32 + 32; ++c) {
            float v = ws[c * K_ + k];
            ss = fmaf(v, v, ss);
        }
        xf[q * 64 + k] = ss;
    }
    __syncthreads();
    if (tid < 64) {
        float tot = xf[tid] + xf[64 + tid] + xf[128 + tid] + xf[192 + tid];
        xf[256 + tid] = 1.f / fmaxf(sqrtf(tot), EPS_);
    }
    __syncthreads();
    for (int i = tid; i < C_ * K_; i += 256) ws[i] *= xf[256 + (i & 63)];
    __syncthreads();

    // role mappings
    const int pq  = tid & 15, cq = tid >> 4;   // loader
    const int pg  = tid & 15, kg = tid >> 4;   // GEMM1: k = kg*4+kq, p = pg*4+..
    const int kg2 = tid & 15, cg = tid >> 4;   // GEMM2: k = kg2 + 16*kq, c = cg*8+m
    const int pN  = tid >> 2, qN = tid & 3;    // softmax: pixel pN, quarter qN
    const int kS  = tid & 63, part = tid >> 6; // sasum

    const int xc1 = 2 * ((kg >> 1) & 1);       // GEMM1 staging rotation (bit3 of k)
    const int bS  = (kg2 >> 3) & 1;            // GEMM2 s-row rotation bit
    const int xcS = 2 * ((kS >> 3) & 1);       // sasum row rotation

    ull acc2[4][8];
    #pragma unroll
    for (int a = 0; a < 4; ++a)
        #pragma unroll
        for (int b = 0; b < 8; ++b) acc2[a][b] = 0ull;
    float sasum_reg = 0.f;

    const float* xbase = x + (size_t)n * C_ * P_ + ps * 1024;
    float* lb = logits_out + (size_t)n * K_ * P_ + ps * 1024;

    for (int sub = 0; sub < 16; ++sub) {
        const int p0 = sub * 64;

        // ---- load raw x tile [c][p] (float4) + per-pixel sumsq partials ----
        {
            const float* xp = xbase + p0 + pq * 4;
            float s0 = 0.f, s1 = 0.f, s2 = 0.f, s3 = 0.f;
            #pragma unroll
            for (int i = 0; i < 8; ++i) {
                int c = cq + 16 * i;
                float4 v = *(const float4*)(xp + (size_t)c * P_);
                *(float4*)(xf + c * XF_STR + pq * 4) = v;
                s0 = fmaf(v.x, v.x, s0);
                s1 = fmaf(v.y, v.y, s1);
                s2 = fmaf(v.z, v.z, s2);
                s3 = fmaf(v.w, v.w, s3);
            }
            *(float4*)(sas + cq * 64 + pq * 4) = make_float4(s0, s1, s2, s3);
        }
        __syncthreads();

        // ---- invn (t<64) overlaps GEMM1 ----
        if (tid < 64) {
            float tot = 0.f;
            #pragma unroll
            for (int q = 0; q < 16; ++q) tot += sas[q * 64 + tid];
            float nr = sqrtf(tot);
            nrm[tid]  = nr;
            invv[tid] = 1.f / fmaxf(nr, EPS_);
        }

        // ---- GEMM1: dot[4k x 4p] over 128 c (raw x, LDS.128) ----
        ull a0[4], a1[4];
        #pragma unroll
        for (int kq = 0; kq < 4; ++kq) { a0[kq] = 0ull; a1[kq] = 0ull; }
        #pragma unroll 4
        for (int c = 0; c < C_; ++c) {
            ulonglong2 xp2 = *(const ulonglong2*)(xf + c * XF_STR + pg * 4);
            float4 w4 = *(const float4*)(ws + c * K_ + kg * 4);
            ull w;
            w = pk2(w4.x, w4.x); FMA2_(a0[0], w, xp2.x); FMA2_(a1[0], w, xp2.y);
            w = pk2(w4.y, w4.y); FMA2_(a0[1], w, xp2.x); FMA2_(a1[1], w, xp2.y);
            w = pk2(w4.z, w4.z); FMA2_(a0[2], w, xp2.x); FMA2_(a1[2], w, xp2.y);
            w = pk2(w4.w, w4.w); FMA2_(a0[3], w, xp2.x); FMA2_(a1[3], w, xp2.y);
        }
        __syncthreads();   // invn ready; sas scratch free

        // ---- scale by invn, write logits gmem + rotated sas staging ----
        {
            float i0 = invv[pg * 4 + 0];
            float i1 = invv[pg * 4 + 1];
            float i2 = invv[pg * 4 + 2];
            float i3 = invv[pg * 4 + 3];
            const int cA = (pg * 4 + xc1) & 63;
            const int cB = (pg * 4 + 2 + xc1) & 63;
            #pragma unroll
            for (int kq = 0; kq < 4; ++kq) {
                float l0, l1, l2, l3;
                upk2(a0[kq], l0, l1);
                upk2(a1[kq], l2, l3);
                l0 *= i0; l1 *= i1; l2 *= i2; l3 *= i3;
                int k = kg * 4 + kq;
                *(float4*)(lb + (size_t)k * P_ + p0 + pg * 4) = make_float4(l0, l1, l2, l3);
                *(float2*)(sas + k * SA_STR + cA) = make_float2(l0, l1);
                *(float2*)(sas + k * SA_STR + cB) = make_float2(l2, l3);
            }
        }
        __syncthreads();

        // ---- softmax over k per pixel (rotated reads/writes); fold invn ----
        {
            const int pA = pN;
            const int pB = (pN + 2) & 63;
            float lv[16];
            float m = -3.4e38f;
            #pragma unroll
            for (int i = 0; i < 16; ++i) {
                int k = qN + 4 * i;
                int col = ((i >> 1) & 1) ? pB : pA;
                float t = (sas[k * SA_STR + col] + bs[k]) * ALPHA_;
                lv[i] = t; m = fmaxf(m, t);
            }
            m = fmaxf(m, __shfl_xor_sync(0xffffffffu, m, 1));
            m = fmaxf(m, __shfl_xor_sync(0xffffffffu, m, 2));
            float s = 0.f;
            #pragma unroll
            for (int i = 0; i < 16; ++i) {
                float e = __expf(lv[i] - m);
                lv[i] = e; s += e;
            }
            s += __shfl_xor_sync(0xffffffffu, s, 1);
            s += __shfl_xor_sync(0xffffffffu, s, 2);
            float rsi = (1.f / s) * invv[pN];    // fold invn into sa
            #pragma unroll
            for (int i = 0; i < 16; ++i) {
                int k = qN + 4 * i;
                int col = ((i >> 1) & 1) ? pB : pA;
                sas[k * SA_STR + col] = lv[i] * rsi;
            }
        }
        __syncthreads();

        // ---- sasum partial: Σp sa = Σ stored * nrm[p] (undo fold+rotation) ----
        {
            float s = 0.f;
            #pragma unroll
            for (int i = 0; i < 16; ++i) {
                int p = part * 16 + i;
                int col = (p + xcS) & 63;
                s = fmaf(sas[kS * SA_STR + col], nrm[p], s);
            }
            sasum_reg += s;
        }

        // ---- GEMM2: acc2[4k x 8c] over 32 p-pairs (conflict-free s-loads) ----
        {
            #pragma unroll 2
            for (int pp = 0; pp < 32; ++pp) {
                const int sc = ((pp + bS) & 31) << 1;
                ull s0 = *(const ull*)(sas + (kg2 +  0) * SA_STR + sc);
                ull s1 = *(const ull*)(sas + (kg2 + 16) * SA_STR + sc);
                ull s2 = *(const ull*)(sas + (kg2 + 32) * SA_STR + sc);
                ull s3 = *(const ull*)(sas + (kg2 + 48) * SA_STR + sc);
                ull xv0 = *(const ull*)(xf + (cg * 8 + 0) * XF_STR + 2 * pp);
                ull xv1 = *(const ull*)(xf + (cg * 8 + 1) * XF_STR + 2 * pp);
                ull xv2 = *(const ull*)(xf + (cg * 8 + 2) * XF_STR + 2 * pp);
                ull xv3 = *(const ull*)(xf + (cg * 8 + 3) * XF_STR + 2 * pp);
                ull xv4 = *(const ull*)(xf + (cg * 8 + 4) * XF_STR + 2 * pp);
                ull xv5 = *(const ull*)(xf + (cg * 8 + 5) * XF_STR + 2 * pp);
                ull xv6 = *(const ull*)(xf + (cg * 8 + 6) * XF_STR + 2 * pp);
                ull xv7 = *(const ull*)(xf + (cg * 8 + 7) * XF_STR + 2 * pp);
                FMA2_(acc2[0][0], s0, xv0); FMA2_(acc2[0][1], s0, xv1);
                FMA2_(acc2[0][2], s0, xv2); FMA2_(acc2[0][3], s0, xv3);
                FMA2_(acc2[0][4], s0, xv4); FMA2_(acc2[0][5], s0, xv5);
                FMA2_(acc2[0][6], s0, xv6); FMA2_(acc2[0][7], s0, xv7);
                FMA2_(acc2[1][0], s1, xv0); FMA2_(acc2[1][1], s1, xv1);
                FMA2_(acc2[1][2], s1, xv2); FMA2_(acc2[1][3], s1, xv3);
                FMA2_(acc2[1][4], s1, xv4); FMA2_(acc2[1][5], s1, xv5);
                FMA2_(acc2[1][6], s1, xv6); FMA2_(acc2[1][7], s1, xv7);
                FMA2_(acc2[2][0], s2, xv0); FMA2_(acc2[2][1], s2, xv1);
                FMA2_(acc2[2][2], s2, xv2); FMA2_(acc2[2][3], s2, xv3);
                FMA2_(acc2[2][4], s2, xv4); FMA2_(acc2[2][5], s2, xv5);
                FMA2_(acc2[2][6], s2, xv6); FMA2_(acc2[2][7], s2, xv7);
                FMA2_(acc2[3][0], s3, xv0); FMA2_(acc2[3][1], s3, xv1);
                FMA2_(acc2[3][2], s3, xv2); FMA2_(acc2[3][3], s3, xv3);
                FMA2_(acc2[3][4], s3, xv4); FMA2_(acc2[3][5], s3, xv5);
                FMA2_(acc2[3][6], s3, xv6); FMA2_(acc2[3][7], s3, xv7);
            }
        }
        __syncthreads();
    }

    // ---- write GEMM2 split partials (fold p-parity halves) ----
    {
        float* pp = g_partial + ((size_t)(n * 4 + ps) * K_) * C_;
        #pragma unroll
        for (int kq = 0; kq < 4; ++kq) {
            int k = kg2 + 16 * kq;
            #pragma unroll
            for (int m = 0; m < 8; ++m) {
                float u0, u1;
                upk2(acc2[kq][m], u0, u1);
                pp[k * C_ + cg * 8 + m] = u0 + u1;
            }
        }
    }

    // ---- reduce sasum parts ----
    sas[part * 64 + kS] = sasum_reg;
    __syncthreads();
    if (tid < 64)
        g_sasum[(n * 4 + ps) * 64 + tid] =
            sas[tid] + sas[64 + tid] + sas[128 + tid] + sas[192 + tid];
}

// ---------------- kernel D: combine + subtract + intra-norm + global/8 ----------------
__global__ __launch_bounds__(128) void kD(const float* __restrict__ W,
                                          float* __restrict__ vlad_out) {
    __shared__ float red[128];
    const int b = blockIdx.x;
    const int n = b >> 6, k = b & 63, tid = threadIdx.x;

    float sasum = 0.f;
    #pragma unroll
    for (int ps = 0; ps < 4; ++ps) sasum += g_sasum[(n * 4 + ps) * 64 + k];

    float v = 0.f;
    #pragma unroll
    for (int ps = 0; ps < 4; ++ps)
        v += g_partial[((size_t)(n * 4 + ps) * K_ + k) * C_ + tid];
    v = fmaf(-sasum, W[tid * K_ + k], v);

    red[tid] = v * v; __syncthreads();
    #pragma unroll
    for (int o = 64; o > 0; o >>= 1) { if (tid < o) red[tid] += red[tid + o]; __syncthreads(); }
    // intra-norm; global L2 over 64 unit-norm rows is exactly sqrt(64)=8
    float inv = 0.125f / fmaxf(sqrtf(red[0]), EPS_);
    vlad_out[((size_t)n * K_ + k) * C_ + tid] = v * inv;
}

// ---------------- launch ----------------
extern "C" void kernel_launch(void* const* d_in, const int* in_sizes, int n_in,
                              void* d_out, int out_size) {
    const float* x    = (const float*)d_in[0];
    const float* W    = (const float*)d_in[1];
    const float* bias = (const float*)d_in[2];
    float* out        = (float*)d_out;
    float* vlad_out   = out;                               // [64, 8192]
    float* logits_out = out + (size_t)N_ * K_ * C_;        // [64, 64, 4096]

    const int smemM = (C_ * K_ + C_ * XF_STR + K_ * SA_STR + 192) * (int)sizeof(float);
    static bool attr_set = false;
    if (!attr_set) {
        cudaFuncSetAttribute(kMega, cudaFuncAttributeMaxDynamicSharedMemorySize, smemM);
        attr_set = true;
    }

    dim3 gM(4, N_);
    kMega<<<gM, 256, smemM>>>(x, W, bias, logits_out);

    kD<<<N_ * K_, 128>>>(W, vlad_out);
}

// round 11
// speedup vs baseline: 1.3881x; 1.3425x over previous
#include <cuda_runtime.h>
#include <cuda_bf16.h>
#include <cstdint>
#include <math.h>

#define N_    64
#define C_    128
#define K_    64
#define P_    4096
#define ALPHA_ 50.0f
#define EPS_  1e-12f

typedef unsigned long long ull;
typedef unsigned int uint32;

// ---------------- scratch ----------------
__device__ float g_partial[N_ * 4 * K_ * C_];   // [n][ps][k][c]
__device__ float g_sasum[N_ * 4 * K_];          // [n][ps][k]

// ---------------- f32x2 helpers ----------------
__device__ __forceinline__ ull pk2(float a, float b) {
    ull r;
    asm("mov.b64 %0, {%1, %2};" : "=l"(r) : "r"(__float_as_uint(a)), "r"(__float_as_uint(b)));
    return r;
}
__device__ __forceinline__ void upk2(ull v, float& a, float& b) {
    uint32 x, y;
    asm("mov.b64 {%0, %1}, %2;" : "=r"(x), "=r"(y) : "l"(v));
    a = __uint_as_float(x); b = __uint_as_float(y);
}
#define FMA2_(d, a, b) asm("fma.rn.f32x2 %0, %1, %2, %3;" : "=l"(d) : "l"(a), "l"(b), "l"(d))

// ---------------- tensor-op helpers (legacy mma.sync path) ----------------
__device__ __forceinline__ uint32 smem_u32(const void* p) {
    uint32 a;
    asm("{ .reg .u64 t; cvta.to.shared.u64 t, %1; cvt.u32.u64 %0, t; }" : "=r"(a) : "l"(p));
    return a;
}
__device__ __forceinline__ void ldmat_x4(uint32& r0, uint32& r1, uint32& r2, uint32& r3, uint32 addr) {
    asm volatile("ldmatrix.sync.aligned.m8n8.x4.shared.b16 {%0,%1,%2,%3}, [%4];"
                 : "=r"(r0), "=r"(r1), "=r"(r2), "=r"(r3) : "r"(addr));
}
__device__ __forceinline__ void ldmat_x2(uint32& r0, uint32& r1, uint32 addr) {
    asm volatile("ldmatrix.sync.aligned.m8n8.x2.shared.b16 {%0,%1}, [%2];"
                 : "=r"(r0), "=r"(r1) : "r"(addr));
}
__device__ __forceinline__ void mma16816(float& d0, float& d1, float& d2, float& d3,
                                         uint32 a0, uint32 a1, uint32 a2, uint32 a3,
                                         uint32 b0, uint32 b1) {
    asm volatile("mma.sync.aligned.m16n8k16.row.col.f32.bf16.bf16.f32 "
                 "{%0,%1,%2,%3}, {%4,%5,%6,%7}, {%8,%9}, {%0,%1,%2,%3};"
                 : "+f"(d0), "+f"(d1), "+f"(d2), "+f"(d3)
                 : "r"(a0), "r"(a1), "r"(a2), "r"(a3), "r"(b0), "r"(b1));
}

__device__ __forceinline__ uint32 pack_bf16x2(float lo, float hi) {
    __nv_bfloat16 a = __float2bfloat16(lo), b = __float2bfloat16(hi);
    return (uint32)__bfloat16_as_ushort(a) | ((uint32)__bfloat16_as_ushort(b) << 16);
}

// ---------------- smem layout (bytes) ----------------
// X union: xf fp32 [128][68] (34816) OR xa_h/xa_l bf16 [128][72] (2x18432)
// S union: sas fp32 [64][68] (17408)  OR sa_h/sa_l bf16 [64][72]  (2x9216)
#define SM_WS   0
#define SM_X    32768
#define SM_XAL  (SM_X + 18432)
#define SM_S    69632
#define SM_SAL  (SM_S + 9216)
#define SM_BS   88064
#define SM_INV  88320
#define SM_TOT  88576

#define XFS 68       // fp32 stride (floats)
#define SFS 68
#define BROW 144     // bf16 row stride (bytes) = 72 elems

// ---------------- fused mega kernel: grid (4, 64), 256 threads ----------------
__global__ __launch_bounds__(256, 2) void kMega(const float* __restrict__ x,
                                                const float* __restrict__ W,
                                                const float* __restrict__ bias,
                                                float* __restrict__ logits_out) {
    extern __shared__ char smc[];
    float* ws   = (float*)(smc + SM_WS);
    float* xf   = (float*)(smc + SM_X);
    float* sas  = (float*)(smc + SM_S);
    float* bs   = (float*)(smc + SM_BS);
    float* invv = (float*)(smc + SM_INV);

    const int tid = threadIdx.x;
    const int wid = tid >> 5;
    const int lane = tid & 31;
    const int n   = blockIdx.y;
    const int ps  = blockIdx.x;              // 0..3, 1024 px

    const uint32 sbase = smem_u32(smc);

    // ---- prologue: load + column-normalize W ----
    for (int i = tid; i < C_ * K_; i += 256) ws[i] = W[i];
    if (tid < 64) bs[tid] = bias[tid];
    __syncthreads();
    {
        const int k = tid & 63, q = tid >> 6;
        float ss = 0.f;
        #pragma unroll 8
        for (int c = q * 32; c < q * 32 + 32; ++c) {
            float v = ws[c * K_ + k];
            ss = fmaf(v, v, ss);
        }
        xf[q * 64 + k] = ss;
    }
    __syncthreads();
    if (tid < 64) {
        float tot = xf[tid] + xf[64 + tid] + xf[128 + tid] + xf[192 + tid];
        xf[256 + tid] = 1.f / fmaxf(sqrtf(tot), EPS_);
    }
    __syncthreads();
    for (int i = tid; i < C_ * K_; i += 256) ws[i] *= xf[256 + (i & 63)];
    __syncthreads();

    // role mappings
    const int pq = tid & 15, cq = tid >> 4;    // loader: p=pq*4, c=cq+16i
    const int pg = tid & 15, kg = tid >> 4;    // GEMM1: p=pg*4.., k=kg*4..
    const int pN = tid >> 2, qN = tid & 3;     // softmax
    const int kS = tid & 63, part = tid >> 6;  // convert/sasum: row kS, 16 p
    const int cX = tid >> 1, hX = tid & 1;     // xa convert: row cX, 32 p

    float acc[8][4];                           // mma acc: n-tile x 4 (f32)
    #pragma unroll
    for (int a = 0; a < 8; ++a)
        #pragma unroll
        for (int b = 0; b < 4; ++b) acc[a][b] = 0.f;
    float sasum_reg = 0.f;

    const float* xbase = x + (size_t)n * C_ * P_ + ps * 1024;
    float* lb = logits_out + (size_t)n * K_ * P_ + ps * 1024;

    for (int sub = 0; sub < 16; ++sub) {
        const int p0 = sub * 64;

        // ---- A: load raw x tile [c][p] fp32 + sumsq partials ----
        {
            const float* xp = xbase + p0 + pq * 4;
            float s0 = 0.f, s1 = 0.f, s2 = 0.f, s3 = 0.f;
            #pragma unroll
            for (int i = 0; i < 8; ++i) {
                int c = cq + 16 * i;
                float4 v = *(const float4*)(xp + (size_t)c * P_);
                *(float4*)(xf + c * XFS + pq * 4) = v;
                s0 = fmaf(v.x, v.x, s0);
                s1 = fmaf(v.y, v.y, s1);
                s2 = fmaf(v.z, v.z, s2);
                s3 = fmaf(v.w, v.w, s3);
            }
            *(float4*)(sas + cq * 64 + pq * 4) = make_float4(s0, s1, s2, s3);
        }
        __syncthreads();   // (1)

        // ---- B: invn (tid<64), overlaps GEMM1 c-loop ----
        if (tid < 64) {
            float tot = 0.f;
            #pragma unroll
            for (int q = 0; q < 16; ++q) tot += sas[q * 64 + tid];
            invv[tid] = 1.f / fmaxf(sqrtf(tot), EPS_);
        }

        // ---- C: GEMM1 4k x 4p over 128 c ----
        ull a0[4], a1[4];
        #pragma unroll
        for (int kq = 0; kq < 4; ++kq) { a0[kq] = 0ull; a1[kq] = 0ull; }
        #pragma unroll 4
        for (int c = 0; c < C_; ++c) {
            ulonglong2 xp2 = *(const ulonglong2*)(xf + c * XFS + pg * 4);
            float4 w4 = *(const float4*)(ws + c * K_ + kg * 4);
            ull w;
            w = pk2(w4.x, w4.x); FMA2_(a0[0], w, xp2.x); FMA2_(a1[0], w, xp2.y);
            w = pk2(w4.y, w4.y); FMA2_(a0[1], w, xp2.x); FMA2_(a1[1], w, xp2.y);
            w = pk2(w4.z, w4.z); FMA2_(a0[2], w, xp2.x); FMA2_(a1[2], w, xp2.y);
            w = pk2(w4.w, w4.w); FMA2_(a0[3], w, xp2.x); FMA2_(a1[3], w, xp2.y);
        }
        __syncthreads();   // (2) invv ready; sas scratch free

        {
            float i0 = invv[pg * 4 + 0];
            float i1 = invv[pg * 4 + 1];
            float i2 = invv[pg * 4 + 2];
            float i3 = invv[pg * 4 + 3];
            #pragma unroll
            for (int kq = 0; kq < 4; ++kq) {
                float l0, l1, l2, l3;
                upk2(a0[kq], l0, l1);
                upk2(a1[kq], l2, l3);
                l0 *= i0; l1 *= i1; l2 *= i2; l3 *= i3;
                int k = kg * 4 + kq;
                *(float4*)(lb + (size_t)k * P_ + p0 + pg * 4) = make_float4(l0, l1, l2, l3);
                *(float4*)(sas + k * SFS + pg * 4) = make_float4(l0, l1, l2, l3);
            }
        }
        __syncthreads();   // (3)

        // ---- D: softmax over k per pixel (4 thr/pixel), sa fp32 in sas ----
        {
            float lv[16];
            float m = -3.4e38f;
            #pragma unroll
            for (int i = 0; i < 16; ++i) {
                int k = qN + 4 * i;
                float t = (sas[k * SFS + pN] + bs[k]) * ALPHA_;
                lv[i] = t; m = fmaxf(m, t);
            }
            m = fmaxf(m, __shfl_xor_sync(0xffffffffu, m, 1));
            m = fmaxf(m, __shfl_xor_sync(0xffffffffu, m, 2));
            float s = 0.f;
            #pragma unroll
            for (int i = 0; i < 16; ++i) {
                float e = __expf(lv[i] - m);
                lv[i] = e; s += e;
            }
            s += __shfl_xor_sync(0xffffffffu, s, 1);
            s += __shfl_xor_sync(0xffffffffu, s, 2);
            float rs = 1.f / s;
            #pragma unroll
            for (int i = 0; i < 16; ++i)
                sas[(qN + 4 * i) * SFS + pN] = lv[i] * rs;
        }
        __syncthreads();   // (4)

        // ---- F: read fp32 tiles -> regs (+sasum), convert to bf16 hi/lo ----
        float sv[16];       // sa row kS, p = part*16..+15
        float xv[32];       // xf row cX, p = hX*32..+31
        {
            #pragma unroll
            for (int j = 0; j < 4; ++j) {
                float4 v = *(const float4*)(sas + kS * SFS + part * 16 + j * 4);
                sv[j * 4 + 0] = v.x; sv[j * 4 + 1] = v.y;
                sv[j * 4 + 2] = v.z; sv[j * 4 + 3] = v.w;
            }
            #pragma unroll
            for (int j = 0; j < 16; ++j) sasum_reg += sv[j];
            #pragma unroll
            for (int j = 0; j < 8; ++j) {
                float4 v = *(const float4*)(xf + cX * XFS + hX * 32 + j * 4);
                xv[j * 4 + 0] = v.x; xv[j * 4 + 1] = v.y;
                xv[j * 4 + 2] = v.z; xv[j * 4 + 3] = v.w;
            }
        }
        __syncthreads();   // (5) reads done -> safe to overwrite unions

        {
            // sa: fold invn, split hi/lo, store [kS][72] bf16
            uint32 hw[8], lw[8];
            #pragma unroll
            for (int j = 0; j < 8; ++j) {
                float v0 = sv[2 * j]     * invv[part * 16 + 2 * j];
                float v1 = sv[2 * j + 1] * invv[part * 16 + 2 * j + 1];
                __nv_bfloat16 h0 = __float2bfloat16(v0), h1 = __float2bfloat16(v1);
                float r0 = v0 - __bfloat162float(h0), r1 = v1 - __bfloat162float(h1);
                hw[j] = (uint32)__bfloat16_as_ushort(h0) | ((uint32)__bfloat16_as_ushort(h1) << 16);
                lw[j] = pack_bf16x2(r0, r1);
            }
            char* dh = smc + SM_S   + kS * BROW + part * 32;
            char* dl = smc + SM_SAL + kS * BROW + part * 32;
            *(uint4*)dh        = make_uint4(hw[0], hw[1], hw[2], hw[3]);
            *(uint4*)(dh + 16) = make_uint4(hw[4], hw[5], hw[6], hw[7]);
            *(uint4*)dl        = make_uint4(lw[0], lw[1], lw[2], lw[3]);
            *(uint4*)(dl + 16) = make_uint4(lw[4], lw[5], lw[6], lw[7]);

            // xa: raw x split hi/lo, store [cX][72] bf16
            uint32 xh[16], xl[16];
            #pragma unroll
            for (int j = 0; j < 16; ++j) {
                float v0 = xv[2 * j], v1 = xv[2 * j + 1];
                __nv_bfloat16 h0 = __float2bfloat16(v0), h1 = __float2bfloat16(v1);
                float r0 = v0 - __bfloat162float(h0), r1 = v1 - __bfloat162float(h1);
                xh[j] = (uint32)__bfloat16_as_ushort(h0) | ((uint32)__bfloat16_as_ushort(h1) << 16);
                xl[j] = pack_bf16x2(r0, r1);
            }
            char* xdh = smc + SM_X   + cX * BROW + hX * 64;
            char* xdl = smc + SM_XAL + cX * BROW + hX * 64;
            #pragma unroll
            for (int j = 0; j < 4; ++j) {
                *(uint4*)(xdh + 16 * j) = make_uint4(xh[4*j], xh[4*j+1], xh[4*j+2], xh[4*j+3]);
                *(uint4*)(xdl + 16 * j) = make_uint4(xl[4*j], xl[4*j+1], xl[4*j+2], xl[4*j+3]);
            }
        }
        __syncthreads();   // (6) bf16 tiles ready

        // ---- G: tensor GEMM2: warp wid owns m-tile (c rows 16*wid..) ----
        {
            const int c0 = wid * 16;
            const int ar = lane & 15, ah = lane >> 4;
            const int br = lane & 7,  bh = (lane >> 3) & 1;
            uint32 aAddrH = sbase + SM_X   + (c0 + ar) * BROW + ah * 16;
            uint32 aAddrL = sbase + SM_XAL + (c0 + ar) * BROW + ah * 16;
            #pragma unroll
            for (int kc = 0; kc < 4; ++kc) {
                uint32 Ah0, Ah1, Ah2, Ah3, Al0, Al1, Al2, Al3;
                ldmat_x4(Ah0, Ah1, Ah2, Ah3, aAddrH + kc * 32);
                ldmat_x4(Al0, Al1, Al2, Al3, aAddrL + kc * 32);
                #pragma unroll
                for (int nt = 0; nt < 8; ++nt) {
                    uint32 Bh0, Bh1, Bl0, Bl1;
                    uint32 bAddrH = sbase + SM_S   + (nt * 8 + br) * BROW + bh * 16 + kc * 32;
                    uint32 bAddrL = sbase + SM_SAL + (nt * 8 + br) * BROW + bh * 16 + kc * 32;
                    ldmat_x2(Bh0, Bh1, bAddrH);
                    ldmat_x2(Bl0, Bl1, bAddrL);
                    mma16816(acc[nt][0], acc[nt][1], acc[nt][2], acc[nt][3],
                             Ah0, Ah1, Ah2, Ah3, Bh0, Bh1);
                    mma16816(acc[nt][0], acc[nt][1], acc[nt][2], acc[nt][3],
                             Ah0, Ah1, Ah2, Ah3, Bl0, Bl1);
                    mma16816(acc[nt][0], acc[nt][1], acc[nt][2], acc[nt][3],
                             Al0, Al1, Al2, Al3, Bh0, Bh1);
                }
            }
        }
        __syncthreads();   // (7) mma reads done before next A overwrites
    }

    // ---- epilogue: write acc -> g_partial [k][c] ----
    {
        float* pp = g_partial + ((size_t)(n * 4 + ps) * K_) * C_;
        const int row = wid * 16 + (lane >> 2);
        const int col = 2 * (lane & 3);
        #pragma unroll
        for (int nt = 0; nt < 8; ++nt) {
            int k0 = nt * 8 + col;
            pp[(k0    ) * C_ + row    ] = acc[nt][0];
            pp[(k0 + 1) * C_ + row    ] = acc[nt][1];
            pp[(k0    ) * C_ + row + 8] = acc[nt][2];
            pp[(k0 + 1) * C_ + row + 8] = acc[nt][3];
        }
    }

    // ---- sasum reduce (S region free as fp32 scratch) ----
    sas[part * 64 + kS] = sasum_reg;
    __syncthreads();
    if (tid < 64)
        g_sasum[(n * 4 + ps) * 64 + tid] =
            sas[tid] + sas[64 + tid] + sas[128 + tid] + sas[192 + tid];
}

// ---------------- kernel D: combine + subtract + intra-norm + global/8 ----------------
__global__ __launch_bounds__(128) void kD(const float* __restrict__ W,
                                          float* __restrict__ vlad_out) {
    __shared__ float red[128];
    const int b = blockIdx.x;
    const int n = b >> 6, k = b & 63, tid = threadIdx.x;

    float sasum = 0.f;
    #pragma unroll
    for (int ps = 0; ps < 4; ++ps) sasum += g_sasum[(n * 4 + ps) * 64 + k];

    float v = 0.f;
    #pragma unroll
    for (int ps = 0; ps < 4; ++ps)
        v += g_partial[((size_t)(n * 4 + ps) * K_ + k) * C_ + tid];
    v = fmaf(-sasum, W[tid * K_ + k], v);

    red[tid] = v * v; __syncthreads();
    #pragma unroll
    for (int o = 64; o > 0; o >>= 1) { if (tid < o) red[tid] += red[tid + o]; __syncthreads(); }
    // intra-norm; global L2 over 64 unit-norm rows is exactly sqrt(64)=8
    float inv = 0.125f / fmaxf(sqrtf(red[0]), EPS_);
    vlad_out[((size_t)n * K_ + k) * C_ + tid] = v * inv;
}

// ---------------- launch ----------------
extern "C" void kernel_launch(void* const* d_in, const int* in_sizes, int n_in,
                              void* d_out, int out_size) {
    const float* x    = (const float*)d_in[0];
    const float* W    = (const float*)d_in[1];
    const float* bias = (const float*)d_in[2];
    float* out        = (float*)d_out;
    float* vlad_out   = out;                               // [64, 8192]
    float* logits_out = out + (size_t)N_ * K_ * C_;        // [64, 64, 4096]

    static bool attr_set = false;
    if (!attr_set) {
        cudaFuncSetAttribute(kMega, cudaFuncAttributeMaxDynamicSharedMemorySize, SM_TOT);
        attr_set = true;
    }

    dim3 gM(4, N_);
    kMega<<<gM, 256, SM_TOT>>>(x, W, bias, logits_out);

    kD<<<N_ * K_, 128>>>(W, vlad_out);
}

// round 13
// speedup vs baseline: 1.9410x; 1.3983x over previous
#include <cuda_runtime.h>
#include <cuda_bf16.h>
#include <cstdint>
#include <math.h>

#define N_    64
#define C_    128
#define K_    64
#define P_    4096
#define ALPHA_ 50.0f
#define EPS_  1e-12f

typedef unsigned long long ull;
typedef unsigned int uint32;

// ---------------- scratch ----------------
__device__ float g_partial[N_ * 4 * K_ * C_];   // [n][ps][k][c]
__device__ float g_sasum[N_ * 4 * K_];          // [n][ps][k]

// ---------------- helpers ----------------
__device__ __forceinline__ uint32 smem_u32(const void* p) {
    uint32 a;
    asm("{ .reg .u64 t; cvta.to.shared.u64 t, %1; cvt.u32.u64 %0, t; }" : "=r"(a) : "l"(p));
    return a;
}
__device__ __forceinline__ void ldmat_x4(uint32& r0, uint32& r1, uint32& r2, uint32& r3, uint32 addr) {
    asm volatile("ldmatrix.sync.aligned.m8n8.x4.shared.b16 {%0,%1,%2,%3}, [%4];"
                 : "=r"(r0), "=r"(r1), "=r"(r2), "=r"(r3) : "r"(addr));
}
__device__ __forceinline__ void ldmat_x2(uint32& r0, uint32& r1, uint32 addr) {
    asm volatile("ldmatrix.sync.aligned.m8n8.x2.shared.b16 {%0,%1}, [%2];"
                 : "=r"(r0), "=r"(r1) : "r"(addr));
}
__device__ __forceinline__ void ldmat_x2t(uint32& r0, uint32& r1, uint32 addr) {
    asm volatile("ldmatrix.sync.aligned.m8n8.x2.trans.shared.b16 {%0,%1}, [%2];"
                 : "=r"(r0), "=r"(r1) : "r"(addr));
}
__device__ __forceinline__ void mma16816(float& d0, float& d1, float& d2, float& d3,
                                         uint32 a0, uint32 a1, uint32 a2, uint32 a3,
                                         uint32 b0, uint32 b1) {
    asm volatile("mma.sync.aligned.m16n8k16.row.col.f32.bf16.bf16.f32 "
                 "{%0,%1,%2,%3}, {%4,%5,%6,%7}, {%8,%9}, {%0,%1,%2,%3};"
                 : "+f"(d0), "+f"(d1), "+f"(d2), "+f"(d3)
                 : "r"(a0), "r"(a1), "r"(a2), "r"(a3), "r"(b0), "r"(b1));
}
__device__ __forceinline__ uint32 pack_bf16x2(float lo, float hi) {
    __nv_bfloat16 a = __float2bfloat16(lo), b = __float2bfloat16(hi);
    return (uint32)__bfloat16_as_ushort(a) | ((uint32)__bfloat16_as_ushort(b) << 16);
}
__device__ __forceinline__ void split_hl(float v, float& h, float& l) {
    __nv_bfloat16 hb = __float2bfloat16(v);
    h = __bfloat162float(hb);
    l = v - h;
}

// ---------------- smem layout (bytes) ----------------
#define SM_WNTH 0                 // WnT bf16 hi [64 k][128 c] rows 272B  17408
#define SM_WNTL 17408             // WnT bf16 lo                          17408
#define SM_XAH  34816             // x bf16 hi [128 c][64 p] rows 144B    18432
#define SM_XAL  53248             // x bf16 lo                            18432
#define SM_S    71680             // union: sas fp32 [64][68] (17408) / sa bf16 hi+lo
#define SM_SAL  (SM_S + 9216)
#define SM_BS   90112
#define SM_INV  90368
#define SM_TOT  90624

#define SFS  68      // fp32 sas stride (floats)
#define BROW 144     // x/sa bf16 row stride (bytes)
#define WROW 272     // WnT bf16 row stride (bytes)

// ---------------- fused mega kernel: grid (4, 64), 256 threads ----------------
__global__ __launch_bounds__(256, 2) void kMega(const float* __restrict__ x,
                                                const float* __restrict__ W,
                                                const float* __restrict__ bias,
                                                float* __restrict__ logits_out) {
    extern __shared__ char smc[];
    float* sas  = (float*)(smc + SM_S);
    float* bs   = (float*)(smc + SM_BS);
    float* invv = (float*)(smc + SM_INV);

    const int tid = threadIdx.x;
    const int wid = tid >> 5;
    const int lane = tid & 31;
    const int n   = blockIdx.y;
    const int ps  = blockIdx.x;              // 0..3, 1024 px

    const uint32 sbase = smem_u32(smc);

    // ==== prologue: build WnT bf16 hi/lo [k][c] ====
    {
        float* wtmp = (float*)(smc + SM_XAH);   // fp32 [c][k] scratch (32KB)
        for (int i = tid; i < C_ * K_; i += 256) wtmp[i] = W[i];
        if (tid < 64) bs[tid] = bias[tid];
        __syncthreads();
        {
            const int kk = tid & 63, q = tid >> 6;
            float ss = 0.f;
            #pragma unroll 8
            for (int c = q * 32; c < q * 32 + 32; ++c) {
                float v = wtmp[c * K_ + kk];
                ss = fmaf(v, v, ss);
            }
            sas[q * 64 + kk] = ss;
        }
        __syncthreads();
        if (tid < 64) {
            float tot = sas[tid] + sas[64 + tid] + sas[128 + tid] + sas[192 + tid];
            sas[512 + tid] = 1.f / fmaxf(sqrtf(tot), EPS_);
        }
        __syncthreads();
        {
            const int kk = tid & 63, q = tid >> 6;
            float ik = sas[512 + kk];
            #pragma unroll
            for (int j = 0; j < 16; ++j) {
                int c0 = q * 32 + 2 * j;
                float v0 = wtmp[c0 * K_ + kk] * ik;
                float v1 = wtmp[(c0 + 1) * K_ + kk] * ik;
                float h0, l0, h1, l1;
                split_hl(v0, h0, l0);
                split_hl(v1, h1, l1);
                *(uint32*)(smc + SM_WNTH + kk * WROW + c0 * 2) = pack_bf16x2(h0, h1);
                *(uint32*)(smc + SM_WNTL + kk * WROW + c0 * 2) = pack_bf16x2(l0, l1);
            }
        }
        __syncthreads();
    }

    // role mappings
    const int pq = tid & 15, cq = tid >> 4;    // loader
    const int pN = tid >> 2, qN = tid & 3;     // softmax
    const int kS = tid & 63, part = tid >> 6;  // sa convert/sasum

    float acc[8][4];                           // GEMM2 accum (persistent)
    #pragma unroll
    for (int a = 0; a < 8; ++a)
        #pragma unroll
        for (int b = 0; b < 4; ++b) acc[a][b] = 0.f;
    float sasum_reg = 0.f;

    const float* xbase = x + (size_t)n * C_ * P_ + ps * 1024;
    float* lb = logits_out + (size_t)n * K_ * P_ + ps * 1024;

    for (int sub = 0; sub < 16; ++sub) {
        const int p0 = sub * 64;

        // ---- A: load gmem x -> bf16 hi/lo [c][p] directly + sumsq ----
        {
            const float* xp = xbase + p0 + pq * 4;
            float s0 = 0.f, s1 = 0.f, s2 = 0.f, s3 = 0.f;
            #pragma unroll
            for (int i = 0; i < 8; ++i) {
                int c = cq + 16 * i;
                float4 v = *(const float4*)(xp + (size_t)c * P_);
                s0 = fmaf(v.x, v.x, s0);
                s1 = fmaf(v.y, v.y, s1);
                s2 = fmaf(v.z, v.z, s2);
                s3 = fmaf(v.w, v.w, s3);
                float hx, lx, hy, ly, hz, lz, hw, lw;
                split_hl(v.x, hx, lx); split_hl(v.y, hy, ly);
                split_hl(v.z, hz, lz); split_hl(v.w, hw, lw);
                uint2 hv = make_uint2(pack_bf16x2(hx, hy), pack_bf16x2(hz, hw));
                uint2 lv = make_uint2(pack_bf16x2(lx, ly), pack_bf16x2(lz, lw));
                *(uint2*)(smc + SM_XAH + c * BROW + pq * 8) = hv;
                *(uint2*)(smc + SM_XAL + c * BROW + pq * 8) = lv;
            }
            *(float4*)(sas + cq * 64 + pq * 4) = make_float4(s0, s1, s2, s3);
        }
        __syncthreads();   // (1)

        // ---- B: invn (tid<64) || GEMM1 tensor: D[k][p] = Wn^T x ----
        if (tid < 64) {
            float tot = 0.f;
            #pragma unroll
            for (int q = 0; q < 16; ++q) tot += sas[q * 64 + tid];
            invv[tid] = 1.f / fmaxf(sqrtf(tot), EPS_);
        }
        float f1[4][4];
        #pragma unroll
        for (int a = 0; a < 4; ++a)
            #pragma unroll
            for (int b = 0; b < 4; ++b) f1[a][b] = 0.f;
        const int k0w = (wid & 3) * 16;
        const int phalf = (wid >> 2) * 32;
        {
            uint32 aH = sbase + SM_WNTH + (k0w + (lane & 15)) * WROW + (lane >> 4) * 16;
            uint32 aL = aH + (SM_WNTL - SM_WNTH);
            uint32 bB = sbase + SM_XAH + (lane & 15) * BROW + phalf * 2;
            #pragma unroll
            for (int kc = 0; kc < 8; ++kc) {
                uint32 Ah0, Ah1, Ah2, Ah3, Al0, Al1, Al2, Al3;
                ldmat_x4(Ah0, Ah1, Ah2, Ah3, aH + kc * 32);
                ldmat_x4(Al0, Al1, Al2, Al3, aL + kc * 32);
                #pragma unroll
                for (int nt = 0; nt < 4; ++nt) {
                    uint32 Bh0, Bh1, Bl0, Bl1;
                    uint32 ba = bB + kc * 16 * BROW + nt * 16;
                    ldmat_x2t(Bh0, Bh1, ba);
                    ldmat_x2t(Bl0, Bl1, ba + (SM_XAL - SM_XAH));
                    mma16816(f1[nt][0], f1[nt][1], f1[nt][2], f1[nt][3],
                             Ah0, Ah1, Ah2, Ah3, Bh0, Bh1);
                    mma16816(f1[nt][0], f1[nt][1], f1[nt][2], f1[nt][3],
                             Ah0, Ah1, Ah2, Ah3, Bl0, Bl1);
                    mma16816(f1[nt][0], f1[nt][1], f1[nt][2], f1[nt][3],
                             Al0, Al1, Al2, Al3, Bh0, Bh1);
                }
            }
        }
        __syncthreads();   // (2) invv ready; sas scratch free

        // ---- C: GEMM1 epilogue: x invn -> sas fp32 [k][p] ----
        {
            const int r0 = k0w + (lane >> 2);
            #pragma unroll
            for (int nt = 0; nt < 4; ++nt) {
                int pc = phalf + nt * 8 + 2 * (lane & 3);
                float i0 = invv[pc], i1 = invv[pc + 1];
                *(float2*)(sas + r0 * SFS + pc)       = make_float2(f1[nt][0] * i0, f1[nt][1] * i1);
                *(float2*)(sas + (r0 + 8) * SFS + pc) = make_float2(f1[nt][2] * i0, f1[nt][3] * i1);
            }
        }
        __syncthreads();   // (3)

        // ---- D: logits -> gmem (coalesced float4) ----
        {
            #pragma unroll
            for (int j = 0; j < 4; ++j) {
                int f = tid * 4 + j;             // 0..1023
                int k = f >> 4, p4 = (f & 15) * 4;
                float4 v = *(const float4*)(sas + k * SFS + p4);
                *(float4*)(lb + (size_t)k * P_ + p0 + p4) = v;
            }
        }
        __syncthreads();   // (4)

        // ---- E: softmax over k per pixel (4 thr/pixel), in place ----
        {
            float lv[16];
            float m = -3.4e38f;
            #pragma unroll
            for (int i = 0; i < 16; ++i) {
                int k = qN + 4 * i;
                float t = (sas[k * SFS + pN] + bs[k]) * ALPHA_;
                lv[i] = t; m = fmaxf(m, t);
            }
            m = fmaxf(m, __shfl_xor_sync(0xffffffffu, m, 1));
            m = fmaxf(m, __shfl_xor_sync(0xffffffffu, m, 2));
            float s = 0.f;
            #pragma unroll
            for (int i = 0; i < 16; ++i) {
                float e = __expf(lv[i] - m);
                lv[i] = e; s += e;
            }
            s += __shfl_xor_sync(0xffffffffu, s, 1);
            s += __shfl_xor_sync(0xffffffffu, s, 2);
            float rs = 1.f / s;
            #pragma unroll
            for (int i = 0; i < 16; ++i)
                sas[(qN + 4 * i) * SFS + pN] = lv[i] * rs;
        }
        __syncthreads();   // (5)

        // ---- F: sa fp32 -> regs (+sasum), convert to bf16 hi/lo (x invn) ----
        float sv[16];
        {
            #pragma unroll
            for (int j = 0; j < 4; ++j) {
                float4 v = *(const float4*)(sas + kS * SFS + part * 16 + j * 4);
                sv[j * 4 + 0] = v.x; sv[j * 4 + 1] = v.y;
                sv[j * 4 + 2] = v.z; sv[j * 4 + 3] = v.w;
            }
            #pragma unroll
            for (int j = 0; j < 16; ++j) sasum_reg += sv[j];
        }
        __syncthreads();   // (6) reads done -> overwrite S union
        {
            uint32 hw[8], lw[8];
            #pragma unroll
            for (int j = 0; j < 8; ++j) {
                // fold invn here: GEMM2 x-tile is RAW x, so sa carries invn[p]
                float v0 = sv[2 * j]     * invv[part * 16 + 2 * j];
                float v1 = sv[2 * j + 1] * invv[part * 16 + 2 * j + 1];
                float h0, l0, h1, l1;
                split_hl(v0, h0, l0);
                split_hl(v1, h1, l1);
                hw[j] = pack_bf16x2(h0, h1);
                lw[j] = pack_bf16x2(l0, l1);
            }
            char* dh = smc + SM_S   + kS * BROW + part * 32;
            char* dl = smc + SM_SAL + kS * BROW + part * 32;
            *(uint4*)dh        = make_uint4(hw[0], hw[1], hw[2], hw[3]);
            *(uint4*)(dh + 16) = make_uint4(hw[4], hw[5], hw[6], hw[7]);
            *(uint4*)dl        = make_uint4(lw[0], lw[1], lw[2], lw[3]);
            *(uint4*)(dl + 16) = make_uint4(lw[4], lw[5], lw[6], lw[7]);
        }
        __syncthreads();   // (7) bf16 sa ready

        // ---- G: GEMM2 tensor: D[c][k] += x sa^T (contraction p) ----
        {
            const int c0 = wid * 16;
            const int ar = lane & 15, ah = lane >> 4;
            uint32 aAddrH = sbase + SM_XAH + (c0 + ar) * BROW + ah * 16;
            uint32 aAddrL = sbase + SM_XAL + (c0 + ar) * BROW + ah * 16;
            #pragma unroll
            for (int kc = 0; kc < 4; ++kc) {
                uint32 Ah0, Ah1, Ah2, Ah3, Al0, Al1, Al2, Al3;
                ldmat_x4(Ah0, Ah1, Ah2, Ah3, aAddrH + kc * 32);
                ldmat_x4(Al0, Al1, Al2, Al3, aAddrL + kc * 32);
                #pragma unroll
                for (int nt = 0; nt < 8; ++nt) {
                    uint32 Bh0, Bh1, Bl0, Bl1;
                    uint32 bAddrH = sbase + SM_S   + (nt * 8 + (lane & 7)) * BROW + ((lane >> 3) & 1) * 16 + kc * 32;
                    uint32 bAddrL = bAddrH + (SM_SAL - SM_S);
                    ldmat_x2(Bh0, Bh1, bAddrH);
                    ldmat_x2(Bl0, Bl1, bAddrL);
                    mma16816(acc[nt][0], acc[nt][1], acc[nt][2], acc[nt][3],
                             Ah0, Ah1, Ah2, Ah3, Bh0, Bh1);
                    mma16816(acc[nt][0], acc[nt][1], acc[nt][2], acc[nt][3],
                             Ah0, Ah1, Ah2, Ah3, Bl0, Bl1);
                    mma16816(acc[nt][0], acc[nt][1], acc[nt][2], acc[nt][3],
                             Al0, Al1, Al2, Al3, Bh0, Bh1);
                }
            }
        }
        __syncthreads();   // (8) mma reads done before next A overwrites
    }

    // ---- epilogue: write acc -> g_partial [k][c] ----
    {
        float* pp = g_partial + ((size_t)(n * 4 + ps) * K_) * C_;
        const int row = wid * 16 + (lane >> 2);
        const int col = 2 * (lane & 3);
        #pragma unroll
        for (int nt = 0; nt < 8; ++nt) {
            int k0 = nt * 8 + col;
            pp[(k0    ) * C_ + row    ] = acc[nt][0];
            pp[(k0 + 1) * C_ + row    ] = acc[nt][1];
            pp[(k0    ) * C_ + row + 8] = acc[nt][2];
            pp[(k0 + 1) * C_ + row + 8] = acc[nt][3];
        }
    }

    // ---- sasum reduce (S region free as fp32 scratch) ----
    sas[part * 64 + kS] = sasum_reg;
    __syncthreads();
    if (tid < 64)
        g_sasum[(n * 4 + ps) * 64 + tid] =
            sas[tid] + sas[64 + tid] + sas[128 + tid] + sas[192 + tid];
}

// ---------------- kernel D: combine + subtract + intra-norm + global/8 ----------------
__global__ __launch_bounds__(128) void kD(const float* __restrict__ W,
                                          float* __restrict__ vlad_out) {
    __shared__ float red[128];
    const int b = blockIdx.x;
    const int n = b >> 6, k = b & 63, tid = threadIdx.x;

    float sasum = 0.f;
    #pragma unroll
    for (int ps = 0; ps < 4; ++ps) sasum += g_sasum[(n * 4 + ps) * 64 + k];

    float v = 0.f;
    #pragma unroll
    for (int ps = 0; ps < 4; ++ps)
        v += g_partial[((size_t)(n * 4 + ps) * K_ + k) * C_ + tid];
    v = fmaf(-sasum, W[tid * K_ + k], v);

    red[tid] = v * v; __syncthreads();
    #pragma unroll
    for (int o = 64; o > 0; o >>= 1) { if (tid < o) red[tid] += red[tid + o]; __syncthreads(); }
    // intra-norm; global L2 over 64 unit-norm rows is exactly sqrt(64)=8
    float inv = 0.125f / fmaxf(sqrtf(red[0]), EPS_);
    vlad_out[((size_t)n * K_ + k) * C_ + tid] = v * inv;
}

// ---------------- launch ----------------
extern "C" void kernel_launch(void* const* d_in, const int* in_sizes, int n_in,
                              void* d_out, int out_size) {
    const float* x    = (const float*)d_in[0];
    const float* W    = (const float*)d_in[1];
    const float* bias = (const float*)d_in[2];
    float* out        = (float*)d_out;
    float* vlad_out   = out;                               // [64, 8192]
    float* logits_out = out + (size_t)N_ * K_ * C_;        // [64, 64, 4096]

    static bool attr_set = false;
    if (!attr_set) {
        cudaFuncSetAttribute(kMega, cudaFuncAttributeMaxDynamicSharedMemorySize, SM_TOT);
        attr_set = true;
    }

    dim3 gM(4, N_);
    kMega<<<gM, 256, SM_TOT>>>(x, W, bias, logits_out);

    kD<<<N_ * K_, 128>>>(W, vlad_out);
}

// round 14
// speedup vs baseline: 2.0562x; 1.0594x over previous
#include <cuda_runtime.h>
#include <cuda_bf16.h>
#include <cstdint>
#include <math.h>

#define N_    64
#define C_    128
#define K_    64
#define P_    4096
#define ALPHA_ 50.0f
#define EPS_  1e-12f

typedef unsigned long long ull;
typedef unsigned int uint32;

// ---------------- scratch ----------------
__device__ float g_partial[N_ * 4 * K_ * C_];   // [n][ps][k][c]
__device__ float g_sasum[N_ * 4 * K_];          // [n][ps][k]

// ---------------- helpers ----------------
__device__ __forceinline__ uint32 smem_u32(const void* p) {
    uint32 a;
    asm("{ .reg .u64 t; cvta.to.shared.u64 t, %1; cvt.u32.u64 %0, t; }" : "=r"(a) : "l"(p));
    return a;
}
__device__ __forceinline__ void ldmat_x4(uint32& r0, uint32& r1, uint32& r2, uint32& r3, uint32 addr) {
    asm volatile("ldmatrix.sync.aligned.m8n8.x4.shared.b16 {%0,%1,%2,%3}, [%4];"
                 : "=r"(r0), "=r"(r1), "=r"(r2), "=r"(r3) : "r"(addr));
}
__device__ __forceinline__ void ldmat_x4t(uint32& r0, uint32& r1, uint32& r2, uint32& r3, uint32 addr) {
    asm volatile("ldmatrix.sync.aligned.m8n8.x4.trans.shared.b16 {%0,%1,%2,%3}, [%4];"
                 : "=r"(r0), "=r"(r1), "=r"(r2), "=r"(r3) : "r"(addr));
}
__device__ __forceinline__ void mma16816(float& d0, float& d1, float& d2, float& d3,
                                         uint32 a0, uint32 a1, uint32 a2, uint32 a3,
                                         uint32 b0, uint32 b1) {
    asm volatile("mma.sync.aligned.m16n8k16.row.col.f32.bf16.bf16.f32 "
                 "{%0,%1,%2,%3}, {%4,%5,%6,%7}, {%8,%9}, {%0,%1,%2,%3};"
                 : "+f"(d0), "+f"(d1), "+f"(d2), "+f"(d3)
                 : "r"(a0), "r"(a1), "r"(a2), "r"(a3), "r"(b0), "r"(b1));
}
__device__ __forceinline__ uint32 pack_bf16x2(float lo, float hi) {
    __nv_bfloat16 a = __float2bfloat16(lo), b = __float2bfloat16(hi);
    return (uint32)__bfloat16_as_ushort(a) | ((uint32)__bfloat16_as_ushort(b) << 16);
}
__device__ __forceinline__ void split_hl(float v, float& h, float& l) {
    __nv_bfloat16 hb = __float2bfloat16(v);
    h = __bfloat162float(hb);
    l = v - h;
}

// ---------------- smem layout (bytes) ----------------
#define SM_WNTH 0                 // WnT bf16 hi [64 k][128 c] rows 272B  17408
#define SM_WNTL 17408             // WnT bf16 lo                          17408
#define SM_XAH  34816             // x bf16 hi [128 c][64 p] rows 144B    18432
#define SM_XAL  53248             // x bf16 lo                            18432
#define SM_S    71680             // sas fp32 [64][68]                    17408
#define SM_SAH  89088             // sa bf16 hi [64 k][64 p] rows 144B     9216
#define SM_SAL  98304             // sa bf16 lo                            9216
#define SM_BS   107520
#define SM_INV  107776
#define SM_TOT  108032

#define SFS  68      // fp32 sas stride (floats)
#define BROW 144     // x/sa bf16 row stride (bytes)
#define WROW 272     // WnT bf16 row stride (bytes)

// ---------------- fused mega kernel: grid (4, 64), 256 threads ----------------
__global__ __launch_bounds__(256, 2) void kMega(const float* __restrict__ x,
                                                const float* __restrict__ W,
                                                const float* __restrict__ bias,
                                                float* __restrict__ logits_out) {
    extern __shared__ char smc[];
    float* sas  = (float*)(smc + SM_S);
    float* bs   = (float*)(smc + SM_BS);
    float* invv = (float*)(smc + SM_INV);

    const int tid = threadIdx.x;
    const int wid = tid >> 5;
    const int lane = tid & 31;
    const int n   = blockIdx.y;
    const int ps  = blockIdx.x;              // 0..3, 1024 px

    const uint32 sbase = smem_u32(smc);

    // ==== prologue: build WnT bf16 hi/lo [k][c] ====
    {
        float* wtmp = (float*)(smc + SM_XAH);   // fp32 [c][k] scratch (32KB)
        for (int i = tid; i < C_ * K_; i += 256) wtmp[i] = W[i];
        if (tid < 64) bs[tid] = bias[tid];
        __syncthreads();
        {
            const int kk = tid & 63, q = tid >> 6;
            float ss = 0.f;
            #pragma unroll 8
            for (int c = q * 32; c < q * 32 + 32; ++c) {
                float v = wtmp[c * K_ + kk];
                ss = fmaf(v, v, ss);
            }
            sas[q * 64 + kk] = ss;
        }
        __syncthreads();
        if (tid < 64) {
            float tot = sas[tid] + sas[64 + tid] + sas[128 + tid] + sas[192 + tid];
            sas[512 + tid] = 1.f / fmaxf(sqrtf(tot), EPS_);
        }
        __syncthreads();
        {
            const int kk = tid & 63, q = tid >> 6;
            float ik = sas[512 + kk];
            #pragma unroll
            for (int j = 0; j < 16; ++j) {
                int c0 = q * 32 + 2 * j;
                float v0 = wtmp[c0 * K_ + kk] * ik;
                float v1 = wtmp[(c0 + 1) * K_ + kk] * ik;
                float h0, l0, h1, l1;
                split_hl(v0, h0, l0);
                split_hl(v1, h1, l1);
                *(uint32*)(smc + SM_WNTH + kk * WROW + c0 * 2) = pack_bf16x2(h0, h1);
                *(uint32*)(smc + SM_WNTL + kk * WROW + c0 * 2) = pack_bf16x2(l0, l1);
            }
        }
        __syncthreads();
    }

    // role mappings
    const int pq = tid & 15, cq = tid >> 4;    // loader
    const int pN = tid >> 2, qN = tid & 3;     // softmax
    const int kS = tid & 63, part = tid >> 6;  // sa convert/sasum

    float acc[8][4];                           // GEMM2 accum (persistent)
    #pragma unroll
    for (int a = 0; a < 8; ++a)
        #pragma unroll
        for (int b = 0; b < 4; ++b) acc[a][b] = 0.f;
    float sasum_reg = 0.f;

    const float* xbase = x + (size_t)n * C_ * P_ + ps * 1024;
    float* lb = logits_out + (size_t)n * K_ * P_ + ps * 1024;

    const int k0w = (wid & 3) * 16;            // GEMM1 warp tile
    const int phalf = (wid >> 2) * 32;

    for (int sub = 0; sub < 16; ++sub) {
        const int p0 = sub * 64;

        // ---- A: load gmem x -> bf16 hi/lo [c][p] directly + sumsq ----
        {
            const float* xp = xbase + p0 + pq * 4;
            float s0 = 0.f, s1 = 0.f, s2 = 0.f, s3 = 0.f;
            #pragma unroll
            for (int i = 0; i < 8; ++i) {
                int c = cq + 16 * i;
                float4 v = *(const float4*)(xp + (size_t)c * P_);
                s0 = fmaf(v.x, v.x, s0);
                s1 = fmaf(v.y, v.y, s1);
                s2 = fmaf(v.z, v.z, s2);
                s3 = fmaf(v.w, v.w, s3);
                float hx, lx, hy, ly, hz, lz, hw, lw;
                split_hl(v.x, hx, lx); split_hl(v.y, hy, ly);
                split_hl(v.z, hz, lz); split_hl(v.w, hw, lw);
                uint2 hv = make_uint2(pack_bf16x2(hx, hy), pack_bf16x2(hz, hw));
                uint2 lv = make_uint2(pack_bf16x2(lx, ly), pack_bf16x2(lz, lw));
                *(uint2*)(smc + SM_XAH + c * BROW + pq * 8) = hv;
                *(uint2*)(smc + SM_XAL + c * BROW + pq * 8) = lv;
            }
            *(float4*)(sas + cq * 64 + pq * 4) = make_float4(s0, s1, s2, s3);
        }
        __syncthreads();   // (1)

        // ---- B: invn (tid<64) || GEMM1 tensor: D[k][p] = Wn^T x ----
        if (tid < 64) {
            float tot = 0.f;
            #pragma unroll
            for (int q = 0; q < 16; ++q) tot += sas[q * 64 + tid];
            invv[tid] = 1.f / fmaxf(sqrtf(tot), EPS_);
        }
        float f1[4][4];
        #pragma unroll
        for (int a = 0; a < 4; ++a)
            #pragma unroll
            for (int b = 0; b < 4; ++b) f1[a][b] = 0.f;
        {
            uint32 aH = sbase + SM_WNTH + (k0w + (lane & 15)) * WROW + (lane >> 4) * 16;
            uint32 aL = aH + (SM_WNTL - SM_WNTH);
            // B (x) trans loads: x4t covers contraction rows kcp*32 + lane (32 rows)
            uint32 bB = sbase + SM_XAH + lane * BROW + phalf * 2;
            #pragma unroll
            for (int kcp = 0; kcp < 4; ++kcp) {
                uint32 AhA0, AhA1, AhA2, AhA3, AhB0, AhB1, AhB2, AhB3;
                uint32 AlA0, AlA1, AlA2, AlA3, AlB0, AlB1, AlB2, AlB3;
                ldmat_x4(AhA0, AhA1, AhA2, AhA3, aH + (2 * kcp) * 32);
                ldmat_x4(AhB0, AhB1, AhB2, AhB3, aH + (2 * kcp + 1) * 32);
                ldmat_x4(AlA0, AlA1, AlA2, AlA3, aL + (2 * kcp) * 32);
                ldmat_x4(AlB0, AlB1, AlB2, AlB3, aL + (2 * kcp + 1) * 32);
                #pragma unroll
                for (int nt = 0; nt < 4; ++nt) {
                    uint32 Bh0, Bh1, Bh2, Bh3, Bl0, Bl1, Bl2, Bl3;
                    uint32 ba = bB + kcp * 32 * BROW + nt * 16;
                    ldmat_x4t(Bh0, Bh1, Bh2, Bh3, ba);
                    ldmat_x4t(Bl0, Bl1, Bl2, Bl3, ba + (SM_XAL - SM_XAH));
                    mma16816(f1[nt][0], f1[nt][1], f1[nt][2], f1[nt][3],
                             AhA0, AhA1, AhA2, AhA3, Bh0, Bh1);
                    mma16816(f1[nt][0], f1[nt][1], f1[nt][2], f1[nt][3],
                             AhA0, AhA1, AhA2, AhA3, Bl0, Bl1);
                    mma16816(f1[nt][0], f1[nt][1], f1[nt][2], f1[nt][3],
                             AlA0, AlA1, AlA2, AlA3, Bh0, Bh1);
                    mma16816(f1[nt][0], f1[nt][1], f1[nt][2], f1[nt][3],
                             AhB0, AhB1, AhB2, AhB3, Bh2, Bh3);
                    mma16816(f1[nt][0], f1[nt][1], f1[nt][2], f1[nt][3],
                             AhB0, AhB1, AhB2, AhB3, Bl2, Bl3);
                    mma16816(f1[nt][0], f1[nt][1], f1[nt][2], f1[nt][3],
                             AlB0, AlB1, AlB2, AlB3, Bh2, Bh3);
                }
            }
        }
        __syncthreads();   // (2) invv ready; sas scratch free

        // ---- C: epilogue: x invn -> sas fp32 [k][p] AND logits -> gmem ----
        {
            const int r0 = k0w + (lane >> 2);
            #pragma unroll
            for (int nt = 0; nt < 4; ++nt) {
                int pc = phalf + nt * 8 + 2 * (lane & 3);
                float i0 = invv[pc], i1 = invv[pc + 1];
                float2 lo = make_float2(f1[nt][0] * i0, f1[nt][1] * i1);
                float2 hi = make_float2(f1[nt][2] * i0, f1[nt][3] * i1);
                *(float2*)(sas + r0 * SFS + pc)       = lo;
                *(float2*)(sas + (r0 + 8) * SFS + pc) = hi;
                *(float2*)(lb + (size_t)r0 * P_ + p0 + pc)       = lo;
                *(float2*)(lb + (size_t)(r0 + 8) * P_ + p0 + pc) = hi;
            }
        }
        __syncthreads();   // (3)

        // ---- E: softmax over k per pixel (4 thr/pixel), in place ----
        {
            float lv[16];
            float m = -3.4e38f;
            #pragma unroll
            for (int i = 0; i < 16; ++i) {
                int k = qN + 4 * i;
                float t = (sas[k * SFS + pN] + bs[k]) * ALPHA_;
                lv[i] = t; m = fmaxf(m, t);
            }
            m = fmaxf(m, __shfl_xor_sync(0xffffffffu, m, 1));
            m = fmaxf(m, __shfl_xor_sync(0xffffffffu, m, 2));
            float s = 0.f;
            #pragma unroll
            for (int i = 0; i < 16; ++i) {
                float e = __expf(lv[i] - m);
                lv[i] = e; s += e;
            }
            s += __shfl_xor_sync(0xffffffffu, s, 1);
            s += __shfl_xor_sync(0xffffffffu, s, 2);
            float rs = 1.f / s;
            #pragma unroll
            for (int i = 0; i < 16; ++i)
                sas[(qN + 4 * i) * SFS + pN] = lv[i] * rs;
        }
        __syncthreads();   // (4)

        // ---- F: sa fp32 -> sasum + bf16 hi/lo (x invn) into SEPARATE region ----
        {
            float sv[16];
            #pragma unroll
            for (int j = 0; j < 4; ++j) {
                float4 v = *(const float4*)(sas + kS * SFS + part * 16 + j * 4);
                sv[j * 4 + 0] = v.x; sv[j * 4 + 1] = v.y;
                sv[j * 4 + 2] = v.z; sv[j * 4 + 3] = v.w;
            }
            #pragma unroll
            for (int j = 0; j < 16; ++j) sasum_reg += sv[j];

            uint32 hw[8], lw[8];
            #pragma unroll
            for (int j = 0; j < 8; ++j) {
                // fold invn: GEMM2 x-tile is RAW x, so sa carries invn[p]
                float v0 = sv[2 * j]     * invv[part * 16 + 2 * j];
                float v1 = sv[2 * j + 1] * invv[part * 16 + 2 * j + 1];
                float h0, l0, h1, l1;
                split_hl(v0, h0, l0);
                split_hl(v1, h1, l1);
                hw[j] = pack_bf16x2(h0, h1);
                lw[j] = pack_bf16x2(l0, l1);
            }
            char* dh = smc + SM_SAH + kS * BROW + part * 32;
            char* dl = smc + SM_SAL + kS * BROW + part * 32;
            *(uint4*)dh        = make_uint4(hw[0], hw[1], hw[2], hw[3]);
            *(uint4*)(dh + 16) = make_uint4(hw[4], hw[5], hw[6], hw[7]);
            *(uint4*)dl        = make_uint4(lw[0], lw[1], lw[2], lw[3]);
            *(uint4*)(dl + 16) = make_uint4(lw[4], lw[5], lw[6], lw[7]);
        }
        __syncthreads();   // (5) bf16 sa ready

        // ---- G: GEMM2 tensor: D[c][k] += x sa^T (contraction p) ----
        {
            const int c0 = wid * 16;
            const int ar = lane & 15, ah = lane >> 4;
            uint32 aAddrH = sbase + SM_XAH + (c0 + ar) * BROW + ah * 16;
            uint32 aAddrL = sbase + SM_XAL + (c0 + ar) * BROW + ah * 16;
            // B x4: matrices (rows ntp*16+(lane>>4)*8+(lane&7), half (lane>>3)&1)
            uint32 bRow = (lane >> 4) * 8 + (lane & 7);
            uint32 bHalf = ((lane >> 3) & 1) * 16;
            #pragma unroll
            for (int kc = 0; kc < 4; ++kc) {
                uint32 Ah0, Ah1, Ah2, Ah3, Al0, Al1, Al2, Al3;
                ldmat_x4(Ah0, Ah1, Ah2, Ah3, aAddrH + kc * 32);
                ldmat_x4(Al0, Al1, Al2, Al3, aAddrL + kc * 32);
                #pragma unroll
                for (int ntp = 0; ntp < 4; ++ntp) {
                    uint32 Bh0, Bh1, Bh2, Bh3, Bl0, Bl1, Bl2, Bl3;
                    uint32 baH = sbase + SM_SAH + (ntp * 16 + bRow) * BROW + bHalf + kc * 32;
                    uint32 baL = baH + (SM_SAL - SM_SAH);
                    ldmat_x4(Bh0, Bh1, Bh2, Bh3, baH);
                    ldmat_x4(Bl0, Bl1, Bl2, Bl3, baL);
                    int ntA = 2 * ntp, ntB = 2 * ntp + 1;
                    mma16816(acc[ntA][0], acc[ntA][1], acc[ntA][2], acc[ntA][3],
                             Ah0, Ah1, Ah2, Ah3, Bh0, Bh1);
                    mma16816(acc[ntA][0], acc[ntA][1], acc[ntA][2], acc[ntA][3],
                             Ah0, Ah1, Ah2, Ah3, Bl0, Bl1);
                    mma16816(acc[ntA][0], acc[ntA][1], acc[ntA][2], acc[ntA][3],
                             Al0, Al1, Al2, Al3, Bh0, Bh1);
                    mma16816(acc[ntB][0], acc[ntB][1], acc[ntB][2], acc[ntB][3],
                             Ah0, Ah1, Ah2, Ah3, Bh2, Bh3);
                    mma16816(acc[ntB][0], acc[ntB][1], acc[ntB][2], acc[ntB][3],
                             Ah0, Ah1, Ah2, Ah3, Bl2, Bl3);
                    mma16816(acc[ntB][0], acc[ntB][1], acc[ntB][2], acc[ntB][3],
                             Al0, Al1, Al2, Al3, Bh2, Bh3);
                }
            }
        }
        __syncthreads();   // (6) mma reads done before next A overwrites
    }

    // ---- epilogue: write acc -> g_partial [k][c] ----
    {
        float* pp = g_partial + ((size_t)(n * 4 + ps) * K_) * C_;
        const int row = wid * 16 + (lane >> 2);
        const int col = 2 * (lane & 3);
        #pragma unroll
        for (int nt = 0; nt < 8; ++nt) {
            int k0 = nt * 8 + col;
            pp[(k0    ) * C_ + row    ] = acc[nt][0];
            pp[(k0 + 1) * C_ + row    ] = acc[nt][1];
            pp[(k0    ) * C_ + row + 8] = acc[nt][2];
            pp[(k0 + 1) * C_ + row + 8] = acc[nt][3];
        }
    }

    // ---- sasum reduce (sas free as fp32 scratch) ----
    sas[part * 64 + kS] = sasum_reg;
    __syncthreads();
    if (tid < 64)
        g_sasum[(n * 4 + ps) * 64 + tid] =
            sas[tid] + sas[64 + tid] + sas[128 + tid] + sas[192 + tid];
}

// ---------------- kernel D: combine + subtract + intra-norm + global/8 ----------------
__global__ __launch_bounds__(128) void kD(const float* __restrict__ W,
                                          float* __restrict__ vlad_out) {
    __shared__ float red[128];
    const int b = blockIdx.x;
    const int n = b >> 6, k = b & 63, tid = threadIdx.x;

    float sasum = 0.f;
    #pragma unroll
    for (int ps = 0; ps < 4; ++ps) sasum += g_sasum[(n * 4 + ps) * 64 + k];

    float v = 0.f;
    #pragma unroll
    for (int ps = 0; ps < 4; ++ps)
        v += g_partial[((size_t)(n * 4 + ps) * K_ + k) * C_ + tid];
    v = fmaf(-sasum, W[tid * K_ + k], v);

    red[tid] = v * v; __syncthreads();
    #pragma unroll
    for (int o = 64; o > 0; o >>= 1) { if (tid < o) red[tid] += red[tid + o]; __syncthreads(); }
    // intra-norm; global L2 over 64 unit-norm rows is exactly sqrt(64)=8
    float inv = 0.125f / fmaxf(sqrtf(red[0]), EPS_);
    vlad_out[((size_t)n * K_ + k) * C_ + tid] = v * inv;
}

// ---------------- launch ----------------
extern "C" void kernel_launch(void* const* d_in, const int* in_sizes, int n_in,
                              void* d_out, int out_size) {
    const float* x    = (const float*)d_in[0];
    const float* W    = (const float*)d_in[1];
    const float* bias = (const float*)d_in[2];
    float* out        = (float*)d_out;
    float* vlad_out   = out;                               // [64, 8192]
    float* logits_out = out + (size_t)N_ * K_ * C_;        // [64, 64, 4096]

    static bool attr_set = false;
    if (!attr_set) {
        cudaFuncSetAttribute(kMega, cudaFuncAttributeMaxDynamicSharedMemorySize, SM_TOT);
        attr_set = true;
    }

    dim3 gM(4, N_);
    kMega<<<gM, 256, SM_TOT>>>(x, W, bias, logits_out);

    kD<<<N_ * K_, 128>>>(W, vlad_out);
}

// round 15
// speedup vs baseline: 2.1223x; 1.0322x over previous
#include <cuda_runtime.h>
#include <cuda_bf16.h>
#include <cstdint>
#include <math.h>

#define N_    64
#define C_    128
#define K_    64
#define P_    4096
#define ALPHA_ 50.0f
#define EPS_  1e-12f

typedef unsigned long long ull;
typedef unsigned int uint32;

// ---------------- scratch ----------------
__device__ float g_partial[N_ * 4 * K_ * C_];   // [n][ps][k][c]
__device__ float g_sasum[N_ * 4 * K_];          // [n][ps][k]

// ---------------- helpers ----------------
__device__ __forceinline__ uint32 smem_u32(const void* p) {
    uint32 a;
    asm("{ .reg .u64 t; cvta.to.shared.u64 t, %1; cvt.u32.u64 %0, t; }" : "=r"(a) : "l"(p));
    return a;
}
__device__ __forceinline__ void ldmat_x4(uint32& r0, uint32& r1, uint32& r2, uint32& r3, uint32 addr) {
    asm volatile("ldmatrix.sync.aligned.m8n8.x4.shared.b16 {%0,%1,%2,%3}, [%4];"
                 : "=r"(r0), "=r"(r1), "=r"(r2), "=r"(r3) : "r"(addr));
}
__device__ __forceinline__ void ldmat_x4t(uint32& r0, uint32& r1, uint32& r2, uint32& r3, uint32 addr) {
    asm volatile("ldmatrix.sync.aligned.m8n8.x4.trans.shared.b16 {%0,%1,%2,%3}, [%4];"
                 : "=r"(r0), "=r"(r1), "=r"(r2), "=r"(r3) : "r"(addr));
}
__device__ __forceinline__ void mma16816(float& d0, float& d1, float& d2, float& d3,
                                         uint32 a0, uint32 a1, uint32 a2, uint32 a3,
                                         uint32 b0, uint32 b1) {
    asm volatile("mma.sync.aligned.m16n8k16.row.col.f32.bf16.bf16.f32 "
                 "{%0,%1,%2,%3}, {%4,%5,%6,%7}, {%8,%9}, {%0,%1,%2,%3};"
                 : "+f"(d0), "+f"(d1), "+f"(d2), "+f"(d3)
                 : "r"(a0), "r"(a1), "r"(a2), "r"(a3), "r"(b0), "r"(b1));
}
__device__ __forceinline__ uint32 pack_bf16x2(float lo, float hi) {
    __nv_bfloat16 a = __float2bfloat16(lo), b = __float2bfloat16(hi);
    return (uint32)__bfloat16_as_ushort(a) | ((uint32)__bfloat16_as_ushort(b) << 16);
}
__device__ __forceinline__ void split_hl(float v, float& h, float& l) {
    __nv_bfloat16 hb = __float2bfloat16(v);
    h = __bfloat162float(hb);
    l = v - h;
}
// fast packed split: hw = {bf16(v1),bf16(v0)}, lw = residuals (cvt.rn everywhere)
__device__ __forceinline__ void cvt_pair(float v0, float v1, uint32& hw, uint32& lw) {
    asm("cvt.rn.bf16x2.f32 %0, %1, %2;" : "=r"(hw) : "f"(v1), "f"(v0));
    float h0 = __uint_as_float(hw << 16);
    float h1 = __uint_as_float(hw & 0xFFFF0000u);
    float l0 = v0 - h0, l1 = v1 - h1;
    asm("cvt.rn.bf16x2.f32 %0, %1, %2;" : "=r"(lw) : "f"(l1), "f"(l0));
}

// ---------------- smem layout (bytes) ----------------
#define SM_WNTH 0                 // WnT bf16 hi [64 k][128 c] rows 272B  17408
#define SM_WNTL 17408             // WnT bf16 lo                          17408
#define SM_XAH  34816             // x bf16 hi [128 c][64 p] rows 144B    18432
#define SM_XAL  53248             // x bf16 lo                            18432
#define SM_S    71680             // sas fp32 [64][68]                    17408
#define SM_SAH  89088             // sa bf16 hi [64 k][64 p] rows 144B     9216
#define SM_SAL  98304             // sa bf16 lo                            9216
#define SM_BS   107520
#define SM_INV  107776
#define SM_TOT  108032

#define SFS  68      // fp32 sas stride (floats)
#define BROW 144     // x/sa bf16 row stride (bytes)
#define WROW 272     // WnT bf16 row stride (bytes)

// no-op kernels to shift ncu's -s window onto kMega (launch #6)
__global__ void kNop() {}

// ---------------- fused mega kernel: grid (4, 64), 256 threads ----------------
__global__ __launch_bounds__(256, 2) void kMega(const float* __restrict__ x,
                                                const float* __restrict__ W,
                                                const float* __restrict__ bias,
                                                float* __restrict__ logits_out) {
    extern __shared__ char smc[];
    float* sas  = (float*)(smc + SM_S);
    float* bs   = (float*)(smc + SM_BS);
    float* invv = (float*)(smc + SM_INV);

    const int tid = threadIdx.x;
    const int wid = tid >> 5;
    const int lane = tid & 31;
    const int n   = blockIdx.y;
    const int ps  = blockIdx.x;              // 0..3, 1024 px

    const uint32 sbase = smem_u32(smc);

    // ==== prologue: build WnT bf16 hi/lo [k][c] ====
    {
        float* wtmp = (float*)(smc + SM_XAH);   // fp32 [c][k] scratch (32KB)
        for (int i = tid; i < C_ * K_; i += 256) wtmp[i] = W[i];
        if (tid < 64) bs[tid] = bias[tid];
        __syncthreads();
        {
            const int kk = tid & 63, q = tid >> 6;
            float ss = 0.f;
            #pragma unroll 8
            for (int c = q * 32; c < q * 32 + 32; ++c) {
                float v = wtmp[c * K_ + kk];
                ss = fmaf(v, v, ss);
            }
            sas[q * 64 + kk] = ss;
        }
        __syncthreads();
        if (tid < 64) {
            float tot = sas[tid] + sas[64 + tid] + sas[128 + tid] + sas[192 + tid];
            sas[512 + tid] = 1.f / fmaxf(sqrtf(tot), EPS_);
        }
        __syncthreads();
        {
            const int kk = tid & 63, q = tid >> 6;
            float ik = sas[512 + kk];
            #pragma unroll
            for (int j = 0; j < 16; ++j) {
                int c0 = q * 32 + 2 * j;
                float v0 = wtmp[c0 * K_ + kk] * ik;
                float v1 = wtmp[(c0 + 1) * K_ + kk] * ik;
                float h0, l0, h1, l1;
                split_hl(v0, h0, l0);
                split_hl(v1, h1, l1);
                *(uint32*)(smc + SM_WNTH + kk * WROW + c0 * 2) = pack_bf16x2(h0, h1);
                *(uint32*)(smc + SM_WNTL + kk * WROW + c0 * 2) = pack_bf16x2(l0, l1);
            }
        }
        __syncthreads();
    }

    // role mappings
    const int pq = tid & 15, cq = tid >> 4;    // loader
    const int pN = tid >> 2, qN = tid & 3;     // softmax
    const int kS = tid & 63, part = tid >> 6;  // sa convert/sasum

    float acc[8][4];                           // GEMM2 accum (persistent)
    #pragma unroll
    for (int a = 0; a < 8; ++a)
        #pragma unroll
        for (int b = 0; b < 4; ++b) acc[a][b] = 0.f;
    float sasum_reg = 0.f;

    const float* xbase = x + (size_t)n * C_ * P_ + ps * 1024;
    float* lb = logits_out + (size_t)n * K_ * P_ + ps * 1024;

    const int k0w = (wid & 3) * 16;            // GEMM1 warp tile
    const int phalf = (wid >> 2) * 32;

    for (int sub = 0; sub < 16; ++sub) {
        const int p0 = sub * 64;

        // ---- A: load gmem x -> bf16 hi/lo [c][p] directly + sumsq ----
        {
            const float* xp = xbase + p0 + pq * 4;
            float s0 = 0.f, s1 = 0.f, s2 = 0.f, s3 = 0.f;
            #pragma unroll
            for (int i = 0; i < 8; ++i) {
                int c = cq + 16 * i;
                float4 v = *(const float4*)(xp + (size_t)c * P_);
                s0 = fmaf(v.x, v.x, s0);
                s1 = fmaf(v.y, v.y, s1);
                s2 = fmaf(v.z, v.z, s2);
                s3 = fmaf(v.w, v.w, s3);
                uint2 hv, lv;
                cvt_pair(v.x, v.y, hv.x, lv.x);
                cvt_pair(v.z, v.w, hv.y, lv.y);
                *(uint2*)(smc + SM_XAH + c * BROW + pq * 8) = hv;
                *(uint2*)(smc + SM_XAL + c * BROW + pq * 8) = lv;
            }
            *(float4*)(sas + cq * 64 + pq * 4) = make_float4(s0, s1, s2, s3);
        }
        __syncthreads();   // (1)

        // ---- B: invn (tid<64) || GEMM1 tensor: D[k][p] = Wn^T x ----
        if (tid < 64) {
            float tot = 0.f;
            #pragma unroll
            for (int q = 0; q < 16; ++q) tot += sas[q * 64 + tid];
            invv[tid] = 1.f / fmaxf(sqrtf(tot), EPS_);
        }
        float f1[4][4];
        #pragma unroll
        for (int a = 0; a < 4; ++a)
            #pragma unroll
            for (int b = 0; b < 4; ++b) f1[a][b] = 0.f;
        {
            uint32 aH = sbase + SM_WNTH + (k0w + (lane & 15)) * WROW + (lane >> 4) * 16;
            uint32 aL = aH + (SM_WNTL - SM_WNTH);
            uint32 bB = sbase + SM_XAH + lane * BROW + phalf * 2;
            #pragma unroll
            for (int kcp = 0; kcp < 4; ++kcp) {
                uint32 AhA0, AhA1, AhA2, AhA3, AhB0, AhB1, AhB2, AhB3;
                uint32 AlA0, AlA1, AlA2, AlA3, AlB0, AlB1, AlB2, AlB3;
                ldmat_x4(AhA0, AhA1, AhA2, AhA3, aH + (2 * kcp) * 32);
                ldmat_x4(AhB0, AhB1, AhB2, AhB3, aH + (2 * kcp + 1) * 32);
                ldmat_x4(AlA0, AlA1, AlA2, AlA3, aL + (2 * kcp) * 32);
                ldmat_x4(AlB0, AlB1, AlB2, AlB3, aL + (2 * kcp + 1) * 32);
                #pragma unroll
                for (int nt = 0; nt < 4; ++nt) {
                    uint32 Bh0, Bh1, Bh2, Bh3, Bl0, Bl1, Bl2, Bl3;
                    uint32 ba = bB + kcp * 32 * BROW + nt * 16;
                    ldmat_x4t(Bh0, Bh1, Bh2, Bh3, ba);
                    ldmat_x4t(Bl0, Bl1, Bl2, Bl3, ba + (SM_XAL - SM_XAH));
                    mma16816(f1[nt][0], f1[nt][1], f1[nt][2], f1[nt][3],
                             AhA0, AhA1, AhA2, AhA3, Bh0, Bh1);
                    mma16816(f1[nt][0], f1[nt][1], f1[nt][2], f1[nt][3],
                             AhA0, AhA1, AhA2, AhA3, Bl0, Bl1);
                    mma16816(f1[nt][0], f1[nt][1], f1[nt][2], f1[nt][3],
                             AlA0, AlA1, AlA2, AlA3, Bh0, Bh1);
                    mma16816(f1[nt][0], f1[nt][1], f1[nt][2], f1[nt][3],
                             AhB0, AhB1, AhB2, AhB3, Bh2, Bh3);
                    mma16816(f1[nt][0], f1[nt][1], f1[nt][2], f1[nt][3],
                             AhB0, AhB1, AhB2, AhB3, Bl2, Bl3);
                    mma16816(f1[nt][0], f1[nt][1], f1[nt][2], f1[nt][3],
                             AlB0, AlB1, AlB2, AlB3, Bh2, Bh3);
                }
            }
        }
        __syncthreads();   // (2) invv ready; sas scratch free

        // ---- C: epilogue: x invn -> sas fp32 [k][p] AND logits -> gmem ----
        {
            const int r0 = k0w + (lane >> 2);
            #pragma unroll
            for (int nt = 0; nt < 4; ++nt) {
                int pc = phalf + nt * 8 + 2 * (lane & 3);
                float i0 = invv[pc], i1 = invv[pc + 1];
                float2 lo = make_float2(f1[nt][0] * i0, f1[nt][1] * i1);
                float2 hi = make_float2(f1[nt][2] * i0, f1[nt][3] * i1);
                *(float2*)(sas + r0 * SFS + pc)       = lo;
                *(float2*)(sas + (r0 + 8) * SFS + pc) = hi;
                *(float2*)(lb + (size_t)r0 * P_ + p0 + pc)       = lo;
                *(float2*)(lb + (size_t)(r0 + 8) * P_ + p0 + pc) = hi;
            }
        }
        __syncthreads();   // (3)

        // ---- E: softmax over k per pixel (4 thr/pixel), in place ----
        {
            float lv[16];
            float m = -3.4e38f;
            #pragma unroll
            for (int i = 0; i < 16; ++i) {
                int k = qN + 4 * i;
                float t = (sas[k * SFS + pN] + bs[k]) * ALPHA_;
                lv[i] = t; m = fmaxf(m, t);
            }
            m = fmaxf(m, __shfl_xor_sync(0xffffffffu, m, 1));
            m = fmaxf(m, __shfl_xor_sync(0xffffffffu, m, 2));
            float s = 0.f;
            #pragma unroll
            for (int i = 0; i < 16; ++i) {
                float e = __expf(lv[i] - m);
                lv[i] = e; s += e;
            }
            s += __shfl_xor_sync(0xffffffffu, s, 1);
            s += __shfl_xor_sync(0xffffffffu, s, 2);
            float rs = 1.f / s;
            #pragma unroll
            for (int i = 0; i < 16; ++i)
                sas[(qN + 4 * i) * SFS + pN] = lv[i] * rs;
        }
        __syncthreads();   // (4)

        // ---- F: sa fp32 -> sasum + bf16 hi/lo (x invn) ----
        {
            float sv[16];
            #pragma unroll
            for (int j = 0; j < 4; ++j) {
                float4 v = *(const float4*)(sas + kS * SFS + part * 16 + j * 4);
                sv[j * 4 + 0] = v.x; sv[j * 4 + 1] = v.y;
                sv[j * 4 + 2] = v.z; sv[j * 4 + 3] = v.w;
            }
            #pragma unroll
            for (int j = 0; j < 16; ++j) sasum_reg += sv[j];

            uint32 hw[8], lw[8];
            #pragma unroll
            for (int j = 0; j < 8; ++j) {
                // fold invn: GEMM2 x-tile is RAW x, so sa carries invn[p]
                float v0 = sv[2 * j]     * invv[part * 16 + 2 * j];
                float v1 = sv[2 * j + 1] * invv[part * 16 + 2 * j + 1];
                cvt_pair(v0, v1, hw[j], lw[j]);
            }
            char* dh = smc + SM_SAH + kS * BROW + part * 32;
            char* dl = smc + SM_SAL + kS * BROW + part * 32;
            *(uint4*)dh        = make_uint4(hw[0], hw[1], hw[2], hw[3]);
            *(uint4*)(dh + 16) = make_uint4(hw[4], hw[5], hw[6], hw[7]);
            *(uint4*)dl        = make_uint4(lw[0], lw[1], lw[2], lw[3]);
            *(uint4*)(dl + 16) = make_uint4(lw[4], lw[5], lw[6], lw[7]);
        }
        __syncthreads();   // (5) bf16 sa ready

        // ---- G: GEMM2 tensor: D[c][k] += x sa^T (contraction p) ----
        {
            const int c0 = wid * 16;
            const int ar = lane & 15, ah = lane >> 4;
            uint32 aAddrH = sbase + SM_XAH + (c0 + ar) * BROW + ah * 16;
            uint32 aAddrL = sbase + SM_XAL + (c0 + ar) * BROW + ah * 16;
            uint32 bRow = (lane >> 4) * 8 + (lane & 7);
            uint32 bHalf = ((lane >> 3) & 1) * 16;
            #pragma unroll
            for (int kc = 0; kc < 4; ++kc) {
                uint32 Ah0, Ah1, Ah2, Ah3, Al0, Al1, Al2, Al3;
                ldmat_x4(Ah0, Ah1, Ah2, Ah3, aAddrH + kc * 32);
                ldmat_x4(Al0, Al1, Al2, Al3, aAddrL + kc * 32);
                #pragma unroll
                for (int ntp = 0; ntp < 4; ++ntp) {
                    uint32 Bh0, Bh1, Bh2, Bh3, Bl0, Bl1, Bl2, Bl3;
                    uint32 baH = sbase + SM_SAH + (ntp * 16 + bRow) * BROW + bHalf + kc * 32;
                    uint32 baL = baH + (SM_SAL - SM_SAH);
                    ldmat_x4(Bh0, Bh1, Bh2, Bh3, baH);
                    ldmat_x4(Bl0, Bl1, Bl2, Bl3, baL);
                    int ntA = 2 * ntp, ntB = 2 * ntp + 1;
                    mma16816(acc[ntA][0], acc[ntA][1], acc[ntA][2], acc[ntA][3],
                             Ah0, Ah1, Ah2, Ah3, Bh0, Bh1);
                    mma16816(acc[ntA][0], acc[ntA][1], acc[ntA][2], acc[ntA][3],
                             Ah0, Ah1, Ah2, Ah3, Bl0, Bl1);
                    mma16816(acc[ntA][0], acc[ntA][1], acc[ntA][2], acc[ntA][3],
                             Al0, Al1, Al2, Al3, Bh0, Bh1);
                    mma16816(acc[ntB][0], acc[ntB][1], acc[ntB][2], acc[ntB][3],
                             Ah0, Ah1, Ah2, Ah3, Bh2, Bh3);
                    mma16816(acc[ntB][0], acc[ntB][1], acc[ntB][2], acc[ntB][3],
                             Ah0, Ah1, Ah2, Ah3, Bl2, Bl3);
                    mma16816(acc[ntB][0], acc[ntB][1], acc[ntB][2], acc[ntB][3],
                             Al0, Al1, Al2, Al3, Bh2, Bh3);
                }
            }
        }
        __syncthreads();   // (6) mma reads done before next A overwrites
    }

    // ---- epilogue: write acc -> g_partial [k][c] ----
    {
        float* pp = g_partial + ((size_t)(n * 4 + ps) * K_) * C_;
        const int row = wid * 16 + (lane >> 2);
        const int col = 2 * (lane & 3);
        #pragma unroll
        for (int nt = 0; nt < 8; ++nt) {
            int k0 = nt * 8 + col;
            pp[(k0    ) * C_ + row    ] = acc[nt][0];
            pp[(k0 + 1) * C_ + row    ] = acc[nt][1];
            pp[(k0    ) * C_ + row + 8] = acc[nt][2];
            pp[(k0 + 1) * C_ + row + 8] = acc[nt][3];
        }
    }

    // ---- sasum reduce (sas free as fp32 scratch) ----
    sas[part * 64 + kS] = sasum_reg;
    __syncthreads();
    if (tid < 64)
        g_sasum[(n * 4 + ps) * 64 + tid] =
            sas[tid] + sas[64 + tid] + sas[128 + tid] + sas[192 + tid];
}

// ---------------- kernel D: combine + subtract + intra-norm + global/8 ----------------
__global__ __launch_bounds__(128) void kD(const float* __restrict__ W,
                                          float* __restrict__ vlad_out) {
    __shared__ float red[4];
    const int b = blockIdx.x;
    const int n = b >> 6, k = b & 63, tid = threadIdx.x;
    const int lane = tid & 31, w = tid >> 5;

    float sasum = 0.f;
    #pragma unroll
    for (int ps = 0; ps < 4; ++ps) sasum += g_sasum[(n * 4 + ps) * 64 + k];

    float v = 0.f;
    #pragma unroll
    for (int ps = 0; ps < 4; ++ps)
        v += g_partial[((size_t)(n * 4 + ps) * K_ + k) * C_ + tid];
    v = fmaf(-sasum, W[tid * K_ + k], v);

    float sq = v * v;
    sq += __shfl_xor_sync(0xffffffffu, sq, 16);
    sq += __shfl_xor_sync(0xffffffffu, sq, 8);
    sq += __shfl_xor_sync(0xffffffffu, sq, 4);
    sq += __shfl_xor_sync(0xffffffffu, sq, 2);
    sq += __shfl_xor_sync(0xffffffffu, sq, 1);
    if (lane == 0) red[w] = sq;
    __syncthreads();
    float tot = red[0] + red[1] + red[2] + red[3];
    // intra-norm; global L2 over 64 unit-norm rows is exactly sqrt(64)=8
    float inv = 0.125f / fmaxf(sqrtf(tot), EPS_);
    vlad_out[((size_t)n * K_ + k) * C_ + tid] = v * inv;
}

// ---------------- launch ----------------
extern "C" void kernel_launch(void* const* d_in, const int* in_sizes, int n_in,
                              void* d_out, int out_size) {
    const float* x    = (const float*)d_in[0];
    const float* W    = (const float*)d_in[1];
    const float* bias = (const float*)d_in[2];
    float* out        = (float*)d_out;
    float* vlad_out   = out;                               // [64, 8192]
    float* logits_out = out + (size_t)N_ * K_ * C_;        // [64, 64, 4096]

    static bool attr_set = false;
    if (!attr_set) {
        cudaFuncSetAttribute(kMega, cudaFuncAttributeMaxDynamicSharedMemorySize, SM_TOT);
        attr_set = true;
    }

    // nop padding so ncu -s 5 -c 1 (launch #6) lands on kMega:
    // seq per call: #1 nop, #2 kMega, #3 kD, #4 nop -> #6 = kMega
    kNop<<<1, 32>>>();

    dim3 gM(4, N_);
    kMega<<<gM, 256, SM_TOT>>>(x, W, bias, logits_out);

    kD<<<N_ * K_, 128>>>(W, vlad_out);

    kNop<<<1, 32>>>();
}